// round 1
// baseline (speedup 1.0000x reference)
#include <cuda_runtime.h>

#define EPS 0.001f
#define NF   64
#define CCH  256
#define IH   40
#define IW   40
#define NPIX 1600        // 40*40
#define RTOT 4096        // N*K = 512*8
#define K1   12544       // 49*256
#define HID  512
#define DD   512

// ---- scratch (static __device__ per allocation rules) ----
__device__ float g_imgT[(size_t)NF * NPIX * CCH];   // NHWC images, 104.8 MB
__device__ float g_w1t [(size_t)HID * K1];          // w1 transposed to [o][hw*256+c]
__device__ float g_roi [(size_t)RTOT * K1];         // roi matrix [r][hw*256+c], 205 MB
__device__ float g_h1  [(size_t)RTOT * HID];
__device__ float g_h2  [(size_t)RTOT * DD];

// ---------------- image transpose NCHW -> NHWC ----------------
// per frame: [C=256, P=1600] -> [P=1600, C=256]
__global__ void transpose_img(const float* __restrict__ in)
{
    __shared__ float tile[32][33];
    const int f  = blockIdx.z;
    const float* src = in + (size_t)f * CCH * NPIX;
    float* dst = g_imgT + (size_t)f * NPIX * CCH;
    const int p0 = blockIdx.x * 32;   // pixel block
    const int c0 = blockIdx.y * 32;   // channel block

    const int p = p0 + threadIdx.x;
    #pragma unroll
    for (int i = threadIdx.y; i < 32; i += 8) {
        tile[i][threadIdx.x] = src[(size_t)(c0 + i) * NPIX + p];
    }
    __syncthreads();
    const int c = c0 + threadIdx.x;
    #pragma unroll
    for (int i = threadIdx.y; i < 32; i += 8) {
        dst[(size_t)(p0 + i) * CCH + c] = tile[threadIdx.x][i];
    }
}

// ---------------- w1 transpose [o][c*49+hw] -> [o][hw*256+c] ----------------
__global__ void transpose_w1(const float* __restrict__ w1)
{
    const int o = blockIdx.x;
    const float* src = w1   + (size_t)o * K1;
    float*       dst = g_w1t + (size_t)o * K1;
    for (int k = threadIdx.x; k < K1; k += blockDim.x) {
        const int hw = k >> 8;      // k = hw*256 + c
        const int c  = k & 255;
        dst[k] = __ldg(&src[c * 49 + hw]);
    }
}

// ---------------- bilinear RoIAlign gather ----------------
// block = one roi, 64 threads; thread handles 4 channels (float4)
__global__ void __launch_bounds__(64) roi_gather(const int* __restrict__ kf,
                                                 const float* __restrict__ boxes)
{
    const int r  = blockIdx.x;
    const int c4 = threadIdx.x;      // float4 channel index 0..63
    const int f  = kf[r];
    const float x1 = boxes[r * 4 + 0] * 40.f;
    const float y1 = boxes[r * 4 + 1] * 40.f;
    const float x2 = boxes[r * 4 + 2] * 40.f;
    const float y2 = boxes[r * 4 + 3] * 40.f;
    const float bw = (x2 - x1) * (1.f / 7.f);
    const float bh = (y2 - y1) * (1.f / 7.f);

    const float4* img = (const float4*)(g_imgT + (size_t)f * NPIX * CCH);
    float4* dst = (float4*)(g_roi + (size_t)r * K1);

    for (int h = 0; h < 7; ++h) {
        const float Y = y1 + (h + 0.5f) * bh;
        const float yc = fminf(fmaxf(Y, 0.f), 39.f);
        const int   y0 = (int)yc;
        const int   y1i = min(y0 + 1, 39);
        const float ly = yc - (float)y0;
        for (int w = 0; w < 7; ++w) {
            const float X = x1 + (w + 0.5f) * bw;
            const bool valid = (X > -1.f) && (X < 40.f) && (Y > -1.f) && (Y < 40.f);
            const float xc = fminf(fmaxf(X, 0.f), 39.f);
            const int   x0 = (int)xc;
            const int   x1i = min(x0 + 1, 39);
            const float lx = xc - (float)x0;
            const float w00 = (1.f - ly) * (1.f - lx);
            const float w01 = (1.f - ly) * lx;
            const float w10 = ly * (1.f - lx);
            const float w11 = ly * lx;
            // pixel offsets in float4 units (256 floats = 64 float4 per pixel)
            const int p00 = (y0  * 40 + x0 ) * 64 + c4;
            const int p01 = (y0  * 40 + x1i) * 64 + c4;
            const int p10 = (y1i * 40 + x0 ) * 64 + c4;
            const int p11 = (y1i * 40 + x1i) * 64 + c4;
            const float4 v00 = img[p00];
            const float4 v01 = img[p01];
            const float4 v10 = img[p10];
            const float4 v11 = img[p11];
            float4 o;
            o.x = v00.x * w00 + v01.x * w01 + v10.x * w10 + v11.x * w11;
            o.y = v00.y * w00 + v01.y * w01 + v10.y * w10 + v11.y * w11;
            o.z = v00.z * w00 + v01.z * w01 + v10.z * w10 + v11.z * w11;
            o.w = v00.w * w00 + v01.w * w01 + v10.w * w10 + v11.w * w11;
            if (!valid) { o.x = 0.f; o.y = 0.f; o.z = 0.f; o.w = 0.f; }
            dst[(h * 7 + w) * 64 + c4] = o;
        }
    }
}

// ---------------- GEMM (K-major x K-major) + bias + BN + ReLU ----------------
// C[m][n] = relu( (sum_k A[m][k]*B[n][k] + bias[n] - mean[n]) * g[n]*rsqrt(v[n]+eps) + beta[n] )
// 128x128 block tile, BK=8, 256 threads, 8x8 microtile, fma.rn.f32x2 packed math.
__global__ void __launch_bounds__(256, 2)
gemm_bn_relu(const float* __restrict__ A, const float* __restrict__ B,
             float* __restrict__ C, int M, int N, int K,
             const float* __restrict__ bias, const float* __restrict__ gamma,
             const float* __restrict__ beta, const float* __restrict__ mean,
             const float* __restrict__ var)
{
    __shared__ float As[2][8][128];
    __shared__ float Bs[2][8][128];

    const int tid = threadIdx.x;
    const int tx  = tid & 15;    // col group (8 cols)
    const int ty  = tid >> 4;    // row group (8 rows)
    const int m0  = blockIdx.y * 128;
    const int n0  = blockIdx.x * 128;

    const int ldRow = tid >> 1;        // 0..127
    const int ldCol = (tid & 1) << 2;  // 0 or 4
    const float* Ap = A + (size_t)(m0 + ldRow) * K + ldCol;
    const float* Bp = B + (size_t)(n0 + ldRow) * K + ldCol;

    float4 ra = *(const float4*)Ap;
    float4 rb = *(const float4*)Bp;
    As[0][ldCol + 0][ldRow] = ra.x; As[0][ldCol + 1][ldRow] = ra.y;
    As[0][ldCol + 2][ldRow] = ra.z; As[0][ldCol + 3][ldRow] = ra.w;
    Bs[0][ldCol + 0][ldRow] = rb.x; Bs[0][ldCol + 1][ldRow] = rb.y;
    Bs[0][ldCol + 2][ldRow] = rb.z; Bs[0][ldCol + 3][ldRow] = rb.w;
    __syncthreads();

    unsigned long long acc[8][4];
    #pragma unroll
    for (int i = 0; i < 8; ++i)
        #pragma unroll
        for (int j = 0; j < 4; ++j) acc[i][j] = 0ull;

    const int nT = K >> 3;
    int buf = 0;
    for (int t = 0; t < nT; ++t) {
        if (t + 1 < nT) {
            ra = *(const float4*)(Ap + (t + 1) * 8);
            rb = *(const float4*)(Bp + (t + 1) * 8);
        }
        #pragma unroll
        for (int kk = 0; kk < 8; ++kk) {
            const float4 a0 = *(const float4*)&As[buf][kk][ty * 8];
            const float4 a1 = *(const float4*)&As[buf][kk][ty * 8 + 4];
            const unsigned long long* b64 = (const unsigned long long*)&Bs[buf][kk][tx * 8];
            const unsigned long long b0 = b64[0], b1 = b64[1], b2 = b64[2], b3 = b64[3];
            const float av[8] = {a0.x, a0.y, a0.z, a0.w, a1.x, a1.y, a1.z, a1.w};
            #pragma unroll
            for (int i = 0; i < 8; ++i) {
                unsigned long long ap;
                asm("mov.b64 %0, {%1, %1};" : "=l"(ap) : "f"(av[i]));
                asm("fma.rn.f32x2 %0, %1, %2, %0;" : "+l"(acc[i][0]) : "l"(ap), "l"(b0));
                asm("fma.rn.f32x2 %0, %1, %2, %0;" : "+l"(acc[i][1]) : "l"(ap), "l"(b1));
                asm("fma.rn.f32x2 %0, %1, %2, %0;" : "+l"(acc[i][2]) : "l"(ap), "l"(b2));
                asm("fma.rn.f32x2 %0, %1, %2, %0;" : "+l"(acc[i][3]) : "l"(ap), "l"(b3));
            }
        }
        if (t + 1 < nT) {
            As[buf ^ 1][ldCol + 0][ldRow] = ra.x; As[buf ^ 1][ldCol + 1][ldRow] = ra.y;
            As[buf ^ 1][ldCol + 2][ldRow] = ra.z; As[buf ^ 1][ldCol + 3][ldRow] = ra.w;
            Bs[buf ^ 1][ldCol + 0][ldRow] = rb.x; Bs[buf ^ 1][ldCol + 1][ldRow] = rb.y;
            Bs[buf ^ 1][ldCol + 2][ldRow] = rb.z; Bs[buf ^ 1][ldCol + 3][ldRow] = rb.w;
            __syncthreads();
            buf ^= 1;
        }
    }

    // epilogue: bias + BN + ReLU
    #pragma unroll
    for (int jp = 0; jp < 4; ++jp) {
        const int o = n0 + tx * 8 + jp * 2;
        const float sc0 = gamma[o]     * rsqrtf(var[o]     + EPS);
        const float sc1 = gamma[o + 1] * rsqrtf(var[o + 1] + EPS);
        const float sh0 = beta[o]     - mean[o]     * sc0;
        const float sh1 = beta[o + 1] - mean[o + 1] * sc1;
        const float bs0 = bias[o], bs1 = bias[o + 1];
        #pragma unroll
        for (int i = 0; i < 8; ++i) {
            float lo, hi;
            asm("mov.b64 {%0, %1}, %2;" : "=f"(lo), "=f"(hi) : "l"(acc[i][jp]));
            float2 v;
            v.x = fmaxf((lo + bs0) * sc0 + sh0, 0.f);
            v.y = fmaxf((hi + bs1) * sc1 + sh1, 0.f);
            const int m = m0 + ty * 8 + i;
            *(float2*)&C[(size_t)m * N + o] = v;
        }
    }
}

// ---------------- max over K=8 rows per node ----------------
__global__ void max_over_k(float* __restrict__ out)
{
    const int idx = blockIdx.x * 256 + threadIdx.x;   // 0 .. 512*512-1
    const int n = idx >> 9;
    const int d = idx & 511;
    const float* p = g_h2 + (size_t)n * 8 * DD + d;
    float m = p[0];
    #pragma unroll
    for (int k = 1; k < 8; ++k) m = fmaxf(m, p[(size_t)k * DD]);
    out[idx] = m;
}

// ---------------- launch ----------------
extern "C" void kernel_launch(void* const* d_in, const int* in_sizes, int n_in,
                              void* d_out, int out_size)
{
    const float* images = (const float*)d_in[0];
    const int*   kf     = (const int*)  d_in[1];
    const float* boxes  = (const float*)d_in[2];
    const float* w1     = (const float*)d_in[3];
    const float* b1     = (const float*)d_in[4];
    const float* g1     = (const float*)d_in[5];
    const float* bt1    = (const float*)d_in[6];
    const float* m1     = (const float*)d_in[7];
    const float* v1     = (const float*)d_in[8];
    const float* w2     = (const float*)d_in[9];
    const float* b2     = (const float*)d_in[10];
    const float* g2     = (const float*)d_in[11];
    const float* bt2    = (const float*)d_in[12];
    const float* m2     = (const float*)d_in[13];
    const float* v2     = (const float*)d_in[14];
    float* out = (float*)d_out;

    float *roi, *w1t, *h1, *h2;
    cudaGetSymbolAddress((void**)&roi, g_roi);
    cudaGetSymbolAddress((void**)&w1t, g_w1t);
    cudaGetSymbolAddress((void**)&h1,  g_h1);
    cudaGetSymbolAddress((void**)&h2,  g_h2);

    transpose_img<<<dim3(NPIX / 32, CCH / 32, NF), dim3(32, 8)>>>(images);
    transpose_w1<<<HID, 256>>>(w1);
    roi_gather<<<RTOT, 64>>>(kf, boxes);
    gemm_bn_relu<<<dim3(HID / 128, RTOT / 128), 256>>>(
        roi, w1t, h1, RTOT, HID, K1, b1, g1, bt1, m1, v1);
    gemm_bn_relu<<<dim3(DD / 128, RTOT / 128), 256>>>(
        h1, w2, h2, RTOT, DD, HID, b2, g2, bt2, m2, v2);
    max_over_k<<<(512 * 512) / 256, 256>>>(out);
}

// round 3
// speedup vs baseline: 2.9556x; 2.9556x over previous
#include <cuda_runtime.h>
#include <cstdint>

#define EPS 0.001f
#define NF   64
#define CCH  256
#define NPIX 1600        // 40*40
#define RTOT 4096        // N*K = 512*8
#define K1   12544       // 49*256
#define HID  512
#define DD   512
#define NCHUNK 392       // K1/32
#define TILE_BYTES 16384 // 128 x 32 floats
#define TILE_FLOATS 4096

// ---- scratch (static __device__ per allocation rules) ----
__device__ float g_imgT[(size_t)NF * NPIX * CCH];            // NHWC images
__device__ float g_roi [(size_t)RTOT * K1];                  // row-major roi (tf32 bits)
__device__ float g_w1tT[(size_t)4 * NCHUNK * TILE_FLOATS];   // B frag tiles [ntile][chunk]
__device__ float g_roiT[(size_t)32 * NCHUNK * TILE_FLOATS];  // A frag tiles [mtile][chunk]
__device__ float g_h1  [(size_t)RTOT * HID];
__device__ float g_h2  [(size_t)RTOT * DD];

__device__ __forceinline__ uint32_t f2tf32(float v) {
    uint32_t b; asm("cvt.rna.tf32.f32 %0, %1;" : "=r"(b) : "f"(v)); return b;
}

// ---------------- image transpose NCHW -> NHWC ----------------
__global__ void transpose_img(const float* __restrict__ in)
{
    __shared__ float tile[32][33];
    const int f  = blockIdx.z;
    const float* src = in + (size_t)f * CCH * NPIX;
    float* dst = g_imgT + (size_t)f * NPIX * CCH;
    const int p0 = blockIdx.x * 32;
    const int c0 = blockIdx.y * 32;
    const int p = p0 + threadIdx.x;
    #pragma unroll
    for (int i = threadIdx.y; i < 32; i += 8)
        tile[i][threadIdx.x] = src[(size_t)(c0 + i) * NPIX + p];
    __syncthreads();
    const int c = c0 + threadIdx.x;
    #pragma unroll
    for (int i = threadIdx.y; i < 32; i += 8)
        dst[(size_t)(p0 + i) * CCH + c] = tile[threadIdx.x][i];
}

// ---------------- w1 -> fragment-order B tiles (tf32-rounded) ----------------
// logical: B[n=o][k], k = hw*256 + c, source w1[o][c*49+hw]
// tile (ntile=o>>7, chunk=k>>5); within tile (col=o&127, kk=k&31):
// byte off = (col>>3)*1024 + (kk>>4)*512 + ((col&7)*4 + (kk&3))*16 + ((kk>>3)&1)*8 + ((kk>>2)&1)*4
__global__ void transpose_w1(const float* __restrict__ w1)
{
    const int o = blockIdx.x;
    const int ntile = o >> 7, col = o & 127;
    const float* src = w1 + (size_t)o * K1;
    for (int k = threadIdx.x; k < K1; k += blockDim.x) {
        const int hw = k >> 8, c = k & 255;
        const uint32_t bits = f2tf32(__ldg(&src[c * 49 + hw]));
        const int chunk = k >> 5, kk = k & 31;
        const uint32_t off = (uint32_t)(col >> 3) * 1024 + ((kk >> 4) & 1) * 512
                           + (((col & 7) * 4 + (kk & 3)) * 16)
                           + ((kk >> 3) & 1) * 8 + ((kk >> 2) & 1) * 4;
        *(uint32_t*)((char*)g_w1tT + (size_t)(ntile * NCHUNK + chunk) * TILE_BYTES + off) = bits;
    }
}

// ---------------- bilinear RoIAlign gather (row-major, tf32-rounded) ----------------
__global__ void __launch_bounds__(64) roi_gather(const int* __restrict__ kf,
                                                 const float* __restrict__ boxes)
{
    const int r  = blockIdx.x;
    const int c4 = threadIdx.x;
    const int f  = kf[r];
    const float x1 = boxes[r * 4 + 0] * 40.f;
    const float y1 = boxes[r * 4 + 1] * 40.f;
    const float x2 = boxes[r * 4 + 2] * 40.f;
    const float y2 = boxes[r * 4 + 3] * 40.f;
    const float bw = (x2 - x1) * (1.f / 7.f);
    const float bh = (y2 - y1) * (1.f / 7.f);

    const float4* img = (const float4*)(g_imgT + (size_t)f * NPIX * CCH);
    uint4* dst = (uint4*)(g_roi + (size_t)r * K1);

    for (int h = 0; h < 7; ++h) {
        const float Y = y1 + (h + 0.5f) * bh;
        const float yc = fminf(fmaxf(Y, 0.f), 39.f);
        const int   y0 = (int)yc;
        const int   y1i = min(y0 + 1, 39);
        const float ly = yc - (float)y0;
        for (int w = 0; w < 7; ++w) {
            const float X = x1 + (w + 0.5f) * bw;
            const bool valid = (X > -1.f) && (X < 40.f) && (Y > -1.f) && (Y < 40.f);
            const float xc = fminf(fmaxf(X, 0.f), 39.f);
            const int   x0 = (int)xc;
            const int   x1i = min(x0 + 1, 39);
            const float lx = xc - (float)x0;
            const float w00 = (1.f - ly) * (1.f - lx);
            const float w01 = (1.f - ly) * lx;
            const float w10 = ly * (1.f - lx);
            const float w11 = ly * lx;
            const int p00 = (y0  * 40 + x0 ) * 64 + c4;
            const int p01 = (y0  * 40 + x1i) * 64 + c4;
            const int p10 = (y1i * 40 + x0 ) * 64 + c4;
            const int p11 = (y1i * 40 + x1i) * 64 + c4;
            const float4 v00 = img[p00];
            const float4 v01 = img[p01];
            const float4 v10 = img[p10];
            const float4 v11 = img[p11];
            float4 o;
            o.x = v00.x * w00 + v01.x * w01 + v10.x * w10 + v11.x * w11;
            o.y = v00.y * w00 + v01.y * w01 + v10.y * w10 + v11.y * w11;
            o.z = v00.z * w00 + v01.z * w01 + v10.z * w10 + v11.z * w11;
            o.w = v00.w * w00 + v01.w * w01 + v10.w * w10 + v11.w * w11;
            if (!valid) { o.x = 0.f; o.y = 0.f; o.z = 0.f; o.w = 0.f; }
            uint4 t;
            t.x = f2tf32(o.x); t.y = f2tf32(o.y); t.z = f2tf32(o.z); t.w = f2tf32(o.w);
            dst[(h * 7 + w) * 64 + c4] = t;
        }
    }
}

// ---------------- repack A: row-major -> fragment-order tiles ----------------
// block = (chunk, mtile); smem-staged so both gmem sides are coalesced.
__global__ void __launch_bounds__(256) repack_a()
{
    __shared__ float s[128 * 36];
    const int chunk = blockIdx.x, mtile = blockIdx.y;
    const int tid = threadIdx.x;

    // phase 1: coalesced read of 128x32 tile
    #pragma unroll
    for (int i = 0; i < 4; ++i) {
        const int u = tid + i * 256;         // float4 index, 1024 total
        const int row = u >> 3, kq = u & 7;
        const float4 v = *(const float4*)&g_roi[(size_t)(mtile * 128 + row) * K1 + chunk * 32 + kq * 4];
        *(float4*)&s[row * 36 + kq * 4] = v;
    }
    __syncthreads();

    // phase 2: coalesced fragment-order write
    float* out = g_roiT + (size_t)(mtile * NCHUNK + chunk) * TILE_FLOATS;
    #pragma unroll
    for (int i = 0; i < 4; ++i) {
        const int u = tid + i * 256;         // 16B slot index
        const int sub = u >> 7;              // row>>4
        const int rem = u & 127;
        const int ks = rem >> 5;             // k>>3
        const int ln = rem & 31;
        const int g = ln >> 2, tg = ln & 3;
        const int r = sub * 16 + g;
        const int k = ks * 8 + tg;
        float4 v;
        v.x = s[r * 36 + k];
        v.y = s[(r + 8) * 36 + k];
        v.z = s[r * 36 + k + 4];
        v.w = s[(r + 8) * 36 + k + 4];
        *(float4*)&out[u * 4] = v;
    }
}

// ================= GEMM1: tf32 mma.sync, 128x128x32, 4-stage cp.async =========
#define NSTAGE 4
#define STAGE_BYTES 32768
#define SM_TOTAL (NSTAGE * STAGE_BYTES)

__device__ __forceinline__ void cp16(void* smem_dst, const void* gmem_src) {
    unsigned s = (unsigned)__cvta_generic_to_shared(smem_dst);
    asm volatile("cp.async.cg.shared.global [%0], [%1], 16;" :: "r"(s), "l"(gmem_src));
}
__device__ __forceinline__ void cp_commit() { asm volatile("cp.async.commit_group;"); }
template<int N> __device__ __forceinline__ void cp_wait() {
    asm volatile("cp.async.wait_group %0;" :: "n"(N));
}

__global__ void __launch_bounds__(256, 1)
gemm1_tc(const float* __restrict__ bias, const float* __restrict__ gamma,
         const float* __restrict__ beta, const float* __restrict__ mean,
         const float* __restrict__ var)
{
    extern __shared__ char sm[];
    const int tid = threadIdx.x, lane = tid & 31, wid = tid >> 5;
    const int warp_m = wid >> 1, warp_n = wid & 1;
    const int ntile = blockIdx.x, mtile = blockIdx.y;

    const char* Ag = (const char*)g_roiT + (size_t)mtile * NCHUNK * TILE_BYTES;
    const char* Bg = (const char*)g_w1tT + (size_t)ntile * NCHUNK * TILE_BYTES;

    float acc[2][8][4];
    #pragma unroll
    for (int mt = 0; mt < 2; ++mt)
        #pragma unroll
        for (int nt = 0; nt < 8; ++nt)
            #pragma unroll
            for (int j = 0; j < 4; ++j) acc[mt][nt][j] = 0.f;

    // prologue: stages 0..2
    #pragma unroll
    for (int t = 0; t < 3; ++t) {
        char* sa = sm + t * STAGE_BYTES;
        #pragma unroll
        for (int i = 0; i < 4; ++i) {
            const int off = (tid + i * 256) * 16;
            cp16(sa + off,         Ag + (size_t)t * TILE_BYTES + off);
            cp16(sa + 16384 + off, Bg + (size_t)t * TILE_BYTES + off);
        }
        cp_commit();
    }

    const int aBase = (warp_m * 2) * 2048 + lane * 16;
    const int bBase = 16384 + (warp_n * 8) * 1024 + lane * 16;

    for (int t = 0; t < NCHUNK; ++t) {
        cp_wait<2>();
        __syncthreads();

        // issue stage t+3
        if (t + 3 < NCHUNK) {
            char* sa = sm + ((t + 3) & 3) * STAGE_BYTES;
            #pragma unroll
            for (int i = 0; i < 4; ++i) {
                const int off = (tid + i * 256) * 16;
                cp16(sa + off,         Ag + (size_t)(t + 3) * TILE_BYTES + off);
                cp16(sa + 16384 + off, Bg + (size_t)(t + 3) * TILE_BYTES + off);
            }
        }
        cp_commit();

        const char* S = sm + (t & 3) * STAGE_BYTES;
        #pragma unroll
        for (int kp = 0; kp < 2; ++kp) {
            uint4 bf[8];
            #pragma unroll
            for (int nt = 0; nt < 8; ++nt)
                bf[nt] = *(const uint4*)(S + bBase + nt * 1024 + kp * 512);
            #pragma unroll
            for (int ksh = 0; ksh < 2; ++ksh) {
                const int ks = kp * 2 + ksh;
                uint4 af[2];
                #pragma unroll
                for (int mt = 0; mt < 2; ++mt)
                    af[mt] = *(const uint4*)(S + aBase + mt * 2048 + ks * 512);
                #pragma unroll
                for (int nt = 0; nt < 8; ++nt) {
                    const uint32_t b0 = ksh ? bf[nt].z : bf[nt].x;
                    const uint32_t b1 = ksh ? bf[nt].w : bf[nt].y;
                    #pragma unroll
                    for (int mt = 0; mt < 2; ++mt) {
                        asm volatile(
                            "mma.sync.aligned.m16n8k8.row.col.f32.tf32.tf32.f32 "
                            "{%0,%1,%2,%3}, {%4,%5,%6,%7}, {%8,%9}, {%0,%1,%2,%3};"
                            : "+f"(acc[mt][nt][0]), "+f"(acc[mt][nt][1]),
                              "+f"(acc[mt][nt][2]), "+f"(acc[mt][nt][3])
                            : "r"(af[mt].x), "r"(af[mt].y), "r"(af[mt].z), "r"(af[mt].w),
                              "r"(b0), "r"(b1));
                    }
                }
            }
        }
    }

    // epilogue: bias + BN + ReLU -> g_h1
    const int g = lane >> 2, tg = lane & 3;
    const int m0 = mtile * 128 + warp_m * 32;
    const int n0 = ntile * 128 + warp_n * 64;
    #pragma unroll
    for (int nt = 0; nt < 8; ++nt) {
        const int c0 = n0 + nt * 8 + tg * 2;
        const float s0 = gamma[c0]     * rsqrtf(var[c0]     + EPS);
        const float s1 = gamma[c0 + 1] * rsqrtf(var[c0 + 1] + EPS);
        const float h0 = (bias[c0]     - mean[c0])     * s0 + beta[c0];
        const float h1v = (bias[c0 + 1] - mean[c0 + 1]) * s1 + beta[c0 + 1];
        #pragma unroll
        for (int mt = 0; mt < 2; ++mt) {
            const int r = m0 + mt * 16 + g;
            float2 v;
            v.x = fmaxf(acc[mt][nt][0] * s0 + h0,  0.f);
            v.y = fmaxf(acc[mt][nt][1] * s1 + h1v, 0.f);
            *(float2*)&g_h1[(size_t)r * HID + c0] = v;
            v.x = fmaxf(acc[mt][nt][2] * s0 + h0,  0.f);
            v.y = fmaxf(acc[mt][nt][3] * s1 + h1v, 0.f);
            *(float2*)&g_h1[(size_t)(r + 8) * HID + c0] = v;
        }
    }
}

// ---------------- GEMM2 (SIMT fp32, exact) + bias + BN + ReLU ----------------
__global__ void __launch_bounds__(256, 2)
gemm_bn_relu(const float* __restrict__ A, const float* __restrict__ B,
             float* __restrict__ C, int M, int N, int K,
             const float* __restrict__ bias, const float* __restrict__ gamma,
             const float* __restrict__ beta, const float* __restrict__ mean,
             const float* __restrict__ var)
{
    __shared__ float As[2][8][128];
    __shared__ float Bs[2][8][128];

    const int tid = threadIdx.x;
    const int tx  = tid & 15;
    const int ty  = tid >> 4;
    const int m0  = blockIdx.y * 128;
    const int n0  = blockIdx.x * 128;

    const int ldRow = tid >> 1;
    const int ldCol = (tid & 1) << 2;
    const float* Ap = A + (size_t)(m0 + ldRow) * K + ldCol;
    const float* Bp = B + (size_t)(n0 + ldRow) * K + ldCol;

    float4 ra = *(const float4*)Ap;
    float4 rb = *(const float4*)Bp;
    As[0][ldCol + 0][ldRow] = ra.x; As[0][ldCol + 1][ldRow] = ra.y;
    As[0][ldCol + 2][ldRow] = ra.z; As[0][ldCol + 3][ldRow] = ra.w;
    Bs[0][ldCol + 0][ldRow] = rb.x; Bs[0][ldCol + 1][ldRow] = rb.y;
    Bs[0][ldCol + 2][ldRow] = rb.z; Bs[0][ldCol + 3][ldRow] = rb.w;
    __syncthreads();

    unsigned long long acc[8][4];
    #pragma unroll
    for (int i = 0; i < 8; ++i)
        #pragma unroll
        for (int j = 0; j < 4; ++j) acc[i][j] = 0ull;

    const int nT = K >> 3;
    int buf = 0;
    for (int t = 0; t < nT; ++t) {
        if (t + 1 < nT) {
            ra = *(const float4*)(Ap + (t + 1) * 8);
            rb = *(const float4*)(Bp + (t + 1) * 8);
        }
        #pragma unroll
        for (int kk = 0; kk < 8; ++kk) {
            const float4 a0 = *(const float4*)&As[buf][kk][ty * 8];
            const float4 a1 = *(const float4*)&As[buf][kk][ty * 8 + 4];
            const unsigned long long* b64 = (const unsigned long long*)&Bs[buf][kk][tx * 8];
            const unsigned long long b0 = b64[0], b1 = b64[1], b2 = b64[2], b3 = b64[3];
            const float av[8] = {a0.x, a0.y, a0.z, a0.w, a1.x, a1.y, a1.z, a1.w};
            #pragma unroll
            for (int i = 0; i < 8; ++i) {
                unsigned long long ap;
                asm("mov.b64 %0, {%1, %1};" : "=l"(ap) : "f"(av[i]));
                asm("fma.rn.f32x2 %0, %1, %2, %0;" : "+l"(acc[i][0]) : "l"(ap), "l"(b0));
                asm("fma.rn.f32x2 %0, %1, %2, %0;" : "+l"(acc[i][1]) : "l"(ap), "l"(b1));
                asm("fma.rn.f32x2 %0, %1, %2, %0;" : "+l"(acc[i][2]) : "l"(ap), "l"(b2));
                asm("fma.rn.f32x2 %0, %1, %2, %0;" : "+l"(acc[i][3]) : "l"(ap), "l"(b3));
            }
        }
        if (t + 1 < nT) {
            As[buf ^ 1][ldCol + 0][ldRow] = ra.x; As[buf ^ 1][ldCol + 1][ldRow] = ra.y;
            As[buf ^ 1][ldCol + 2][ldRow] = ra.z; As[buf ^ 1][ldCol + 3][ldRow] = ra.w;
            Bs[buf ^ 1][ldCol + 0][ldRow] = rb.x; Bs[buf ^ 1][ldCol + 1][ldRow] = rb.y;
            Bs[buf ^ 1][ldCol + 2][ldRow] = rb.z; Bs[buf ^ 1][ldCol + 3][ldRow] = rb.w;
            __syncthreads();
            buf ^= 1;
        }
    }

    #pragma unroll
    for (int jp = 0; jp < 4; ++jp) {
        const int o = n0 + tx * 8 + jp * 2;
        const float sc0 = gamma[o]     * rsqrtf(var[o]     + EPS);
        const float sc1 = gamma[o + 1] * rsqrtf(var[o + 1] + EPS);
        const float sh0 = beta[o]     - mean[o]     * sc0;
        const float sh1 = beta[o + 1] - mean[o + 1] * sc1;
        const float bs0 = bias[o], bs1 = bias[o + 1];
        #pragma unroll
        for (int i = 0; i < 8; ++i) {
            float lo, hi;
            asm("mov.b64 {%0, %1}, %2;" : "=f"(lo), "=f"(hi) : "l"(acc[i][jp]));
            float2 v;
            v.x = fmaxf((lo + bs0) * sc0 + sh0, 0.f);
            v.y = fmaxf((hi + bs1) * sc1 + sh1, 0.f);
            const int m = m0 + ty * 8 + i;
            *(float2*)&C[(size_t)m * N + o] = v;
        }
    }
}

// ---------------- max over K=8 rows per node ----------------
__global__ void max_over_k(float* __restrict__ out)
{
    const int idx = blockIdx.x * 256 + threadIdx.x;
    const int n = idx >> 9;
    const int d = idx & 511;
    const float* p = g_h2 + (size_t)n * 8 * DD + d;
    float m = p[0];
    #pragma unroll
    for (int k = 1; k < 8; ++k) m = fmaxf(m, p[(size_t)k * DD]);
    out[idx] = m;
}

// ---------------- launch ----------------
extern "C" void kernel_launch(void* const* d_in, const int* in_sizes, int n_in,
                              void* d_out, int out_size)
{
    const float* images = (const float*)d_in[0];
    const int*   kf     = (const int*)  d_in[1];
    const float* boxes  = (const float*)d_in[2];
    const float* w1     = (const float*)d_in[3];
    const float* b1     = (const float*)d_in[4];
    const float* g1     = (const float*)d_in[5];
    const float* bt1    = (const float*)d_in[6];
    const float* m1     = (const float*)d_in[7];
    const float* v1     = (const float*)d_in[8];
    const float* w2     = (const float*)d_in[9];
    const float* b2     = (const float*)d_in[10];
    const float* g2     = (const float*)d_in[11];
    const float* bt2    = (const float*)d_in[12];
    const float* m2     = (const float*)d_in[13];
    const float* v2     = (const float*)d_in[14];
    float* out = (float*)d_out;

    float *h1, *h2;
    cudaGetSymbolAddress((void**)&h1, g_h1);
    cudaGetSymbolAddress((void**)&h2, g_h2);

    cudaFuncSetAttribute(gemm1_tc, cudaFuncAttributeMaxDynamicSharedMemorySize, SM_TOTAL);

    transpose_img<<<dim3(NPIX / 32, CCH / 32, NF), dim3(32, 8)>>>(images);
    transpose_w1<<<HID, 256>>>(w1);
    roi_gather<<<RTOT, 64>>>(kf, boxes);
    repack_a<<<dim3(NCHUNK, 32), 256>>>();
    gemm1_tc<<<dim3(4, 32), 256, SM_TOTAL>>>(b1, g1, bt1, m1, v1);
    gemm_bn_relu<<<dim3(DD / 128, RTOT / 128), 256>>>(
        h1, w2, h2, RTOT, DD, HID, b2, g2, bt2, m2, v2);
    max_over_k<<<(512 * 512) / 256, 256>>>(out);
}

// round 4
// speedup vs baseline: 3.0364x; 1.0273x over previous
#include <cuda_runtime.h>
#include <cuda_fp16.h>
#include <cstdint>

#define EPS 0.001f
#define NF   64
#define CCH  256
#define NPIX 1600        // 40*40
#define RTOT 4096        // N*K = 512*8
#define K1   12544       // 49*256
#define HID  512
#define DD   512
#define NCHUNK 392       // K1/32
#define TILE_BYTES 16384 // 128 rows x 32 k (tf32), fragment order
#define TILE_FLOATS 4096

// ---- scratch (static __device__ per allocation rules) ----
__device__ __half g_imgH[(size_t)NF * NPIX * CCH];           // NHWC fp16 images (52 MB)
__device__ float  g_w1tT[(size_t)4 * NCHUNK * TILE_FLOATS];  // B1 frag tiles
__device__ float  g_roiT[(size_t)32 * NCHUNK * TILE_FLOATS]; // A1 frag tiles (205 MB)
__device__ float  g_h1T [(size_t)32 * 16 * TILE_FLOATS];     // h1 as A2 frag tiles (8 MB)
__device__ float  g_w2T [(size_t)4 * 16 * TILE_FLOATS];      // B2 frag tiles
__device__ float  g_h2  [(size_t)RTOT * DD];

__device__ __forceinline__ uint32_t f2tf32(float v) {
    uint32_t b; asm("cvt.rna.tf32.f32 %0, %1;" : "=r"(b) : "f"(v)); return b;
}

// ---------------- image transpose NCHW f32 -> NHWC f16 ----------------
// block (32,8): 32 pixels x 64 channels per tile
__global__ void transpose_img(const float* __restrict__ in)
{
    __shared__ float s[64][33];
    const int f  = blockIdx.z;
    const float* src = in + (size_t)f * CCH * NPIX;
    const int p0 = blockIdx.x * 32;
    const int c0 = blockIdx.y * 64;
    #pragma unroll
    for (int i = threadIdx.y; i < 64; i += 8)
        s[i][threadIdx.x] = src[(size_t)(c0 + i) * NPIX + p0 + threadIdx.x];
    __syncthreads();
    __half2* dst = (__half2*)g_imgH + (size_t)f * NPIX * 128 + (c0 >> 1) + threadIdx.x;
    #pragma unroll
    for (int i = threadIdx.y; i < 32; i += 8)
        dst[(size_t)(p0 + i) * 128] =
            __floats2half2_rn(s[2 * threadIdx.x][i], s[2 * threadIdx.x + 1][i]);
}

// ---------------- w1 -> fragment-order B tiles (tf32) ----------------
// B[n=o][k], k = hw*256 + c, source w1[o][c*49+hw]
__global__ void transpose_w1(const float* __restrict__ w1)
{
    const int o = blockIdx.x;
    const int ntile = o >> 7, col = o & 127;
    const float* src = w1 + (size_t)o * K1;
    for (int k = threadIdx.x; k < K1; k += blockDim.x) {
        const int hw = k >> 8, c = k & 255;
        const uint32_t bits = f2tf32(__ldg(&src[c * 49 + hw]));
        const int chunk = k >> 5, kk = k & 31;
        const uint32_t off = (uint32_t)(col >> 3) * 1024 + ((kk >> 4) & 1) * 512
                           + (((col & 7) * 4 + (kk & 3)) * 16)
                           + ((kk >> 3) & 1) * 8 + ((kk >> 2) & 1) * 4;
        *(uint32_t*)((char*)g_w1tT + (size_t)(ntile * NCHUNK + chunk) * TILE_BYTES + off) = bits;
    }
}

// ---------------- w2 -> fragment-order B tiles (tf32) ----------------
__global__ void repack_w2(const float* __restrict__ w2)
{
    const int o = blockIdx.x;
    const int ntile = o >> 7, col = o & 127;
    for (int k = threadIdx.x; k < DD; k += blockDim.x) {
        const uint32_t bits = f2tf32(__ldg(&w2[(size_t)o * DD + k]));
        const int chunk = k >> 5, kk = k & 31;
        const uint32_t off = (uint32_t)(col >> 3) * 1024 + ((kk >> 4) & 1) * 512
                           + (((col & 7) * 4 + (kk & 3)) * 16)
                           + ((kk >> 3) & 1) * 8 + ((kk >> 2) & 1) * 4;
        *(uint32_t*)((char*)g_w2T + (size_t)(ntile * 16 + chunk) * TILE_BYTES + off) = bits;
    }
}

// ---------------- fused RoIAlign gather -> A fragment tiles ----------------
// block = 16 rois (one frag sub-group), 256 threads: rl = tid&15 (roi), cg = tid>>4 (16 ch)
union U8 { uint4 u[2]; __half2 h[8]; };

__global__ void __launch_bounds__(256) roi_gather_frag(const int* __restrict__ kf,
                                                       const float* __restrict__ boxes)
{
    __shared__ float s[16 * 258];
    const int blk = blockIdx.x;                  // 0..255
    const int mtile = blk >> 3, sub = blk & 7;
    const int tid = threadIdx.x;
    const int rl = tid & 15, cg = tid >> 4;
    const int r = blk * 16 + rl;
    const int f = kf[r];
    const float x1 = boxes[r * 4 + 0] * 40.f;
    const float y1 = boxes[r * 4 + 1] * 40.f;
    const float x2 = boxes[r * 4 + 2] * 40.f;
    const float y2 = boxes[r * 4 + 3] * 40.f;
    const float bw = (x2 - x1) * (1.f / 7.f);
    const float bh = (y2 - y1) * (1.f / 7.f);

    const __half2* img = (const __half2*)g_imgH + (size_t)f * NPIX * 128;
    char* outb = (char*)g_roiT + (size_t)mtile * NCHUNK * TILE_BYTES + sub * 2048;
    float* srow = s + rl * 258 + cg * 16;

    for (int h = 0; h < 7; ++h) {
        const float Y = y1 + (h + 0.5f) * bh;
        const float yc = fminf(fmaxf(Y, 0.f), 39.f);
        const int   y0 = (int)yc;
        const int   y1i = min(y0 + 1, 39);
        const float ly = yc - (float)y0;
        for (int w = 0; w < 7; ++w) {
            const float X = x1 + (w + 0.5f) * bw;
            const bool valid = (X > -1.f) && (X < 40.f) && (Y > -1.f) && (Y < 40.f);
            const float xc = fminf(fmaxf(X, 0.f), 39.f);
            const int   x0 = (int)xc;
            const int   x1i = min(x0 + 1, 39);
            const float lx = xc - (float)x0;
            float w00 = (1.f - ly) * (1.f - lx);
            float w01 = (1.f - ly) * lx;
            float w10 = ly * (1.f - lx);
            float w11 = ly * lx;
            if (!valid) { w00 = w01 = w10 = w11 = 0.f; }

            const uint4* q00 = (const uint4*)(img + (y0  * 40 + x0 ) * 128 + cg * 8);
            const uint4* q01 = (const uint4*)(img + (y0  * 40 + x1i) * 128 + cg * 8);
            const uint4* q10 = (const uint4*)(img + (y1i * 40 + x0 ) * 128 + cg * 8);
            const uint4* q11 = (const uint4*)(img + (y1i * 40 + x1i) * 128 + cg * 8);
            U8 c00, c01, c10, c11;
            c00.u[0] = q00[0]; c00.u[1] = q00[1];
            c01.u[0] = q01[0]; c01.u[1] = q01[1];
            c10.u[0] = q10[0]; c10.u[1] = q10[1];
            c11.u[0] = q11[0]; c11.u[1] = q11[1];

            #pragma unroll
            for (int j = 0; j < 8; ++j) {
                const float2 f00 = __half22float2(c00.h[j]);
                const float2 f01 = __half22float2(c01.h[j]);
                const float2 f10 = __half22float2(c10.h[j]);
                const float2 f11 = __half22float2(c11.h[j]);
                float2 o;
                o.x = f00.x * w00 + f01.x * w01 + f10.x * w10 + f11.x * w11;
                o.y = f00.y * w00 + f01.y * w01 + f10.y * w10 + f11.y * w11;
                o.x = __uint_as_float(f2tf32(o.x));
                o.y = __uint_as_float(f2tf32(o.y));
                *(float2*)(srow + 2 * j) = o;
            }
            __syncthreads();

            const int hw = h * 7 + w;
            #pragma unroll
            for (int it = 0; it < 4; ++it) {
                const int u = tid + it * 256;       // slot 0..1023
                const int cc = u >> 7, rem = u & 127;
                const int ks = rem >> 5, ln = rem & 31;
                const int gg = ln >> 2, tg = ln & 3;
                const int ch = cc * 32 + ks * 8 + tg;
                uint4 wv;
                wv.x = __float_as_uint(s[gg * 258 + ch]);
                wv.y = __float_as_uint(s[(gg + 8) * 258 + ch]);
                wv.z = __float_as_uint(s[gg * 258 + ch + 4]);
                wv.w = __float_as_uint(s[(gg + 8) * 258 + ch + 4]);
                *(uint4*)(outb + (size_t)(hw * 8 + cc) * TILE_BYTES + rem * 16) = wv;
            }
            __syncthreads();
        }
    }
}

// ================= generic tf32 MMA GEMM: 128x128x32, 4-stage cp.async =========
#define NSTAGE 4
#define STAGE_BYTES 32768
#define SM_TOTAL (NSTAGE * STAGE_BYTES)

__device__ __forceinline__ void cp16(void* smem_dst, const void* gmem_src) {
    unsigned s = (unsigned)__cvta_generic_to_shared(smem_dst);
    asm volatile("cp.async.cg.shared.global [%0], [%1], 16;" :: "r"(s), "l"(gmem_src));
}
__device__ __forceinline__ void cp_commit() { asm volatile("cp.async.commit_group;"); }
template<int N> __device__ __forceinline__ void cp_wait() {
    asm volatile("cp.async.wait_group %0;" :: "n"(N));
}

__global__ void __launch_bounds__(256, 1)
gemm_tc(const char* __restrict__ Afrag, const char* __restrict__ Bfrag, int nchunk,
        float* __restrict__ outRow, char* __restrict__ outFrag,
        const float* __restrict__ bias, const float* __restrict__ gamma,
        const float* __restrict__ beta, const float* __restrict__ mean,
        const float* __restrict__ var)
{
    extern __shared__ char sm[];
    const int tid = threadIdx.x, lane = tid & 31, wid = tid >> 5;
    const int warp_m = wid >> 1, warp_n = wid & 1;
    const int ntile = blockIdx.x, mtile = blockIdx.y;
    const int Ntot = gridDim.x * 128;

    const char* Ag = Afrag + (size_t)mtile * nchunk * TILE_BYTES;
    const char* Bg = Bfrag + (size_t)ntile * nchunk * TILE_BYTES;

    float acc[2][8][4];
    #pragma unroll
    for (int mt = 0; mt < 2; ++mt)
        #pragma unroll
        for (int nt = 0; nt < 8; ++nt)
            #pragma unroll
            for (int j = 0; j < 4; ++j) acc[mt][nt][j] = 0.f;

    #pragma unroll
    for (int t = 0; t < 3; ++t) {
        char* sa = sm + t * STAGE_BYTES;
        #pragma unroll
        for (int i = 0; i < 4; ++i) {
            const int off = (tid + i * 256) * 16;
            cp16(sa + off,         Ag + (size_t)t * TILE_BYTES + off);
            cp16(sa + 16384 + off, Bg + (size_t)t * TILE_BYTES + off);
        }
        cp_commit();
    }

    const int aBase = (warp_m * 2) * 2048 + lane * 16;
    const int bBase = 16384 + (warp_n * 8) * 1024 + lane * 16;

    for (int t = 0; t < nchunk; ++t) {
        cp_wait<2>();
        __syncthreads();

        if (t + 3 < nchunk) {
            char* sa = sm + ((t + 3) & 3) * STAGE_BYTES;
            #pragma unroll
            for (int i = 0; i < 4; ++i) {
                const int off = (tid + i * 256) * 16;
                cp16(sa + off,         Ag + (size_t)(t + 3) * TILE_BYTES + off);
                cp16(sa + 16384 + off, Bg + (size_t)(t + 3) * TILE_BYTES + off);
            }
        }
        cp_commit();

        const char* S = sm + (t & 3) * STAGE_BYTES;
        #pragma unroll
        for (int kp = 0; kp < 2; ++kp) {
            uint4 bf[8];
            #pragma unroll
            for (int nt = 0; nt < 8; ++nt)
                bf[nt] = *(const uint4*)(S + bBase + nt * 1024 + kp * 512);
            #pragma unroll
            for (int ksh = 0; ksh < 2; ++ksh) {
                const int ks = kp * 2 + ksh;
                uint4 af[2];
                #pragma unroll
                for (int mt = 0; mt < 2; ++mt)
                    af[mt] = *(const uint4*)(S + aBase + mt * 2048 + ks * 512);
                #pragma unroll
                for (int nt = 0; nt < 8; ++nt) {
                    const uint32_t b0 = ksh ? bf[nt].z : bf[nt].x;
                    const uint32_t b1 = ksh ? bf[nt].w : bf[nt].y;
                    #pragma unroll
                    for (int mt = 0; mt < 2; ++mt) {
                        asm volatile(
                            "mma.sync.aligned.m16n8k8.row.col.f32.tf32.tf32.f32 "
                            "{%0,%1,%2,%3}, {%4,%5,%6,%7}, {%8,%9}, {%0,%1,%2,%3};"
                            : "+f"(acc[mt][nt][0]), "+f"(acc[mt][nt][1]),
                              "+f"(acc[mt][nt][2]), "+f"(acc[mt][nt][3])
                            : "r"(af[mt].x), "r"(af[mt].y), "r"(af[mt].z), "r"(af[mt].w),
                              "r"(b0), "r"(b1));
                    }
                }
            }
        }
    }

    const int g = lane >> 2, tg = lane & 3;

    if (outFrag) {
        // stage BN+ReLU tile in smem, then emit A-fragment-order tf32 tiles
        __syncthreads();
        float* st = (float*)sm;   // 128 x 132
        #pragma unroll
        for (int nt = 0; nt < 8; ++nt) {
            const int c0l = warp_n * 64 + nt * 8 + tg * 2;
            const int cg0 = ntile * 128 + c0l;
            const float s0 = gamma[cg0]     * rsqrtf(var[cg0]     + EPS);
            const float s1 = gamma[cg0 + 1] * rsqrtf(var[cg0 + 1] + EPS);
            const float h0  = (bias[cg0]     - mean[cg0])     * s0 + beta[cg0];
            const float h1v = (bias[cg0 + 1] - mean[cg0 + 1]) * s1 + beta[cg0 + 1];
            #pragma unroll
            for (int mt = 0; mt < 2; ++mt) {
                const int rowl = warp_m * 32 + mt * 16 + g;
                float2 v;
                v.x = fmaxf(acc[mt][nt][0] * s0 + h0,  0.f);
                v.y = fmaxf(acc[mt][nt][1] * s1 + h1v, 0.f);
                *(float2*)&st[rowl * 132 + c0l] = v;
                v.x = fmaxf(acc[mt][nt][2] * s0 + h0,  0.f);
                v.y = fmaxf(acc[mt][nt][3] * s1 + h1v, 0.f);
                *(float2*)&st[(rowl + 8) * 132 + c0l] = v;
            }
        }
        __syncthreads();
        char* dst = outFrag + (size_t)(mtile * (gridDim.x * 4) + ntile * 4) * TILE_BYTES;
        #pragma unroll
        for (int it = 0; it < 16; ++it) {
            const int u = tid + it * 256;        // 0..4095
            const int cc = u >> 10, rem = u & 1023;
            const int sub = rem >> 7, r2 = rem & 127;
            const int ks = r2 >> 5, ln = r2 & 31;
            const int gg = ln >> 2, tg2 = ln & 3;
            const int row = sub * 16 + gg;
            const int k = cc * 32 + ks * 8 + tg2;
            uint4 wv;
            wv.x = f2tf32(st[row * 132 + k]);
            wv.y = f2tf32(st[(row + 8) * 132 + k]);
            wv.z = f2tf32(st[row * 132 + k + 4]);
            wv.w = f2tf32(st[(row + 8) * 132 + k + 4]);
            *(uint4*)(dst + (size_t)cc * TILE_BYTES + rem * 16) = wv;
        }
    } else {
        const int m0 = mtile * 128 + warp_m * 32;
        const int n0 = ntile * 128 + warp_n * 64;
        #pragma unroll
        for (int nt = 0; nt < 8; ++nt) {
            const int c0 = n0 + nt * 8 + tg * 2;
            const float s0 = gamma[c0]     * rsqrtf(var[c0]     + EPS);
            const float s1 = gamma[c0 + 1] * rsqrtf(var[c0 + 1] + EPS);
            const float h0  = (bias[c0]     - mean[c0])     * s0 + beta[c0];
            const float h1v = (bias[c0 + 1] - mean[c0 + 1]) * s1 + beta[c0 + 1];
            #pragma unroll
            for (int mt = 0; mt < 2; ++mt) {
                const int rr = m0 + mt * 16 + g;
                float2 v;
                v.x = fmaxf(acc[mt][nt][0] * s0 + h0,  0.f);
                v.y = fmaxf(acc[mt][nt][1] * s1 + h1v, 0.f);
                *(float2*)&outRow[(size_t)rr * Ntot + c0] = v;
                v.x = fmaxf(acc[mt][nt][2] * s0 + h0,  0.f);
                v.y = fmaxf(acc[mt][nt][3] * s1 + h1v, 0.f);
                *(float2*)&outRow[(size_t)(rr + 8) * Ntot + c0] = v;
            }
        }
    }
}

// ---------------- max over K=8 rows per node ----------------
__global__ void max_over_k(float* __restrict__ out)
{
    const int idx = blockIdx.x * 256 + threadIdx.x;
    const int n = idx >> 9;
    const int d = idx & 511;
    const float* p = g_h2 + (size_t)n * 8 * DD + d;
    float m = p[0];
    #pragma unroll
    for (int k = 1; k < 8; ++k) m = fmaxf(m, p[(size_t)k * DD]);
    out[idx] = m;
}

// ---------------- launch ----------------
extern "C" void kernel_launch(void* const* d_in, const int* in_sizes, int n_in,
                              void* d_out, int out_size)
{
    const float* images = (const float*)d_in[0];
    const int*   kf     = (const int*)  d_in[1];
    const float* boxes  = (const float*)d_in[2];
    const float* w1     = (const float*)d_in[3];
    const float* b1     = (const float*)d_in[4];
    const float* g1     = (const float*)d_in[5];
    const float* bt1    = (const float*)d_in[6];
    const float* m1     = (const float*)d_in[7];
    const float* v1     = (const float*)d_in[8];
    const float* w2     = (const float*)d_in[9];
    const float* b2     = (const float*)d_in[10];
    const float* g2     = (const float*)d_in[11];
    const float* bt2    = (const float*)d_in[12];
    const float* m2     = (const float*)d_in[13];
    const float* v2     = (const float*)d_in[14];
    float* out = (float*)d_out;

    char *roiT, *w1tT, *h1T, *w2T;
    float *h2;
    cudaGetSymbolAddress((void**)&roiT, g_roiT);
    cudaGetSymbolAddress((void**)&w1tT, g_w1tT);
    cudaGetSymbolAddress((void**)&h1T,  g_h1T);
    cudaGetSymbolAddress((void**)&w2T,  g_w2T);
    cudaGetSymbolAddress((void**)&h2,   g_h2);

    cudaFuncSetAttribute(gemm_tc, cudaFuncAttributeMaxDynamicSharedMemorySize, SM_TOTAL);

    transpose_img<<<dim3(NPIX / 32, CCH / 64, NF), dim3(32, 8)>>>(images);
    transpose_w1<<<HID, 256>>>(w1);
    repack_w2<<<DD, 128>>>(w2);
    roi_gather_frag<<<256, 256>>>(kf, boxes);
    gemm_tc<<<dim3(4, 32), 256, SM_TOTAL>>>(
        roiT, w1tT, NCHUNK, nullptr, h1T, b1, g1, bt1, m1, v1);
    gemm_tc<<<dim3(4, 32), 256, SM_TOTAL>>>(
        h1T, w2T, 16, h2, nullptr, b2, g2, bt2, m2, v2);
    max_over_k<<<(512 * 512) / 256, 256>>>(out);
}

// round 5
// speedup vs baseline: 3.2635x; 1.0748x over previous
#include <cuda_runtime.h>
#include <cuda_fp16.h>
#include <cstdint>

#define EPS 0.001f
#define NF   64
#define CCH  256
#define NPIX 1600        // 40*40
#define RTOT 4096        // N*K = 512*8
#define K1   12544       // 49*256
#define HID  512
#define DD   512
#define NCHUNK 392       // K1/32
#define TILE_BYTES 16384 // 128 rows x 32 k (tf32), fragment order
#define TILE_FLOATS 4096

// ---- scratch (static __device__ per allocation rules) ----
__device__ __half g_imgH[(size_t)NF * NPIX * CCH];           // NHWC fp16 images (52 MB)
__device__ float  g_w1tT[(size_t)4 * NCHUNK * TILE_FLOATS];  // B1 frag tiles
__device__ float  g_roiT[(size_t)32 * NCHUNK * TILE_FLOATS]; // A1 frag tiles (205 MB)
__device__ float  g_h1T [(size_t)32 * 16 * TILE_FLOATS];     // h1 as A2 frag tiles (8 MB)
__device__ float  g_w2T [(size_t)4 * 16 * TILE_FLOATS];      // B2 frag tiles

__device__ __forceinline__ uint32_t f2tf32(float v) {
    uint32_t b; asm("cvt.rna.tf32.f32 %0, %1;" : "=r"(b) : "f"(v)); return b;
}

// ---------------- image transpose NCHW f32 -> NHWC f16 ----------------
__global__ void transpose_img(const float* __restrict__ in)
{
    __shared__ float s[64][33];
    const int f  = blockIdx.z;
    const float* src = in + (size_t)f * CCH * NPIX;
    const int p0 = blockIdx.x * 32;
    const int c0 = blockIdx.y * 64;
    #pragma unroll
    for (int i = threadIdx.y; i < 64; i += 8)
        s[i][threadIdx.x] = src[(size_t)(c0 + i) * NPIX + p0 + threadIdx.x];
    __syncthreads();
    __half2* dst = (__half2*)g_imgH + (size_t)f * NPIX * 128 + (c0 >> 1) + threadIdx.x;
    #pragma unroll
    for (int i = threadIdx.y; i < 32; i += 8)
        dst[(size_t)(p0 + i) * 128] =
            __floats2half2_rn(s[2 * threadIdx.x][i], s[2 * threadIdx.x + 1][i]);
}

// ---------------- w1 -> fragment-order B tiles (tf32) ----------------
__global__ void transpose_w1(const float* __restrict__ w1)
{
    const int o = blockIdx.x;
    const int ntile = o >> 7, col = o & 127;
    const float* src = w1 + (size_t)o * K1;
    for (int k = threadIdx.x; k < K1; k += blockDim.x) {
        const int hw = k >> 8, c = k & 255;
        const uint32_t bits = f2tf32(__ldg(&src[c * 49 + hw]));
        const int chunk = k >> 5, kk = k & 31;
        const uint32_t off = (uint32_t)(col >> 3) * 1024 + ((kk >> 4) & 1) * 512
                           + (((col & 7) * 4 + (kk & 3)) * 16)
                           + ((kk >> 3) & 1) * 8 + ((kk >> 2) & 1) * 4;
        *(uint32_t*)((char*)g_w1tT + (size_t)(ntile * NCHUNK + chunk) * TILE_BYTES + off) = bits;
    }
}

// ---------------- w2 -> fragment-order B tiles (tf32) ----------------
__global__ void repack_w2(const float* __restrict__ w2)
{
    const int o = blockIdx.x;
    const int ntile = o >> 7, col = o & 127;
    for (int k = threadIdx.x; k < DD; k += blockDim.x) {
        const uint32_t bits = f2tf32(__ldg(&w2[(size_t)o * DD + k]));
        const int chunk = k >> 5, kk = k & 31;
        const uint32_t off = (uint32_t)(col >> 3) * 1024 + ((kk >> 4) & 1) * 512
                           + (((col & 7) * 4 + (kk & 3)) * 16)
                           + ((kk >> 3) & 1) * 8 + ((kk >> 2) & 1) * 4;
        *(uint32_t*)((char*)g_w2T + (size_t)(ntile * 16 + chunk) * TILE_BYTES + off) = bits;
    }
}

// ---------------- fused RoIAlign gather -> A fragment tiles (h-split) ----------------
// grid (256 roi-groups, 7 h); block 256: rl = tid&15 (roi), cg = tid>>4 (16 channels)
union U4 { uint4 u; __half2 h[4]; };

__global__ void __launch_bounds__(256) roi_gather_frag(const int* __restrict__ kf,
                                                       const float* __restrict__ boxes)
{
    __shared__ float s[16 * 258];
    const int blk = blockIdx.x;                  // 0..255
    const int h   = blockIdx.y;                  // 0..6
    const int mtile = blk >> 3, sub = blk & 7;
    const int tid = threadIdx.x;
    const int rl = tid & 15, cg = tid >> 4;
    const int r = blk * 16 + rl;
    const int f = kf[r];
    const float x1 = boxes[r * 4 + 0] * 40.f;
    const float y1 = boxes[r * 4 + 1] * 40.f;
    const float x2 = boxes[r * 4 + 2] * 40.f;
    const float y2 = boxes[r * 4 + 3] * 40.f;
    const float bw = (x2 - x1) * (1.f / 7.f);
    const float bh = (y2 - y1) * (1.f / 7.f);

    const __half2* img = (const __half2*)g_imgH + (size_t)f * NPIX * 128;
    char* outb = (char*)g_roiT + (size_t)mtile * NCHUNK * TILE_BYTES + sub * 2048;
    float* srow = s + rl * 258 + cg * 16;

    const float Y = y1 + (h + 0.5f) * bh;
    const float yc = fminf(fmaxf(Y, 0.f), 39.f);
    const int   y0 = (int)yc;
    const int   y1i = min(y0 + 1, 39);
    const float ly = yc - (float)y0;

    for (int w = 0; w < 7; ++w) {
        const float X = x1 + (w + 0.5f) * bw;
        const bool valid = (X > -1.f) && (X < 40.f) && (Y > -1.f) && (Y < 40.f);
        const float xc = fminf(fmaxf(X, 0.f), 39.f);
        const int   x0 = (int)xc;
        const int   x1i = min(x0 + 1, 39);
        const float lx = xc - (float)x0;
        float w00 = (1.f - ly) * (1.f - lx);
        float w01 = (1.f - ly) * lx;
        float w10 = ly * (1.f - lx);
        float w11 = ly * lx;
        if (!valid) { w00 = w01 = w10 = w11 = 0.f; }

        const uint4* q00 = (const uint4*)(img + (y0  * 40 + x0 ) * 128 + cg * 8);
        const uint4* q01 = (const uint4*)(img + (y0  * 40 + x1i) * 128 + cg * 8);
        const uint4* q10 = (const uint4*)(img + (y1i * 40 + x0 ) * 128 + cg * 8);
        const uint4* q11 = (const uint4*)(img + (y1i * 40 + x1i) * 128 + cg * 8);

        #pragma unroll
        for (int half = 0; half < 2; ++half) {
            U4 c00, c01, c10, c11;
            c00.u = q00[half]; c01.u = q01[half];
            c10.u = q10[half]; c11.u = q11[half];
            #pragma unroll
            for (int j = 0; j < 4; ++j) {
                const float2 f00 = __half22float2(c00.h[j]);
                const float2 f01 = __half22float2(c01.h[j]);
                const float2 f10 = __half22float2(c10.h[j]);
                const float2 f11 = __half22float2(c11.h[j]);
                float2 o;
                o.x = f00.x * w00 + f01.x * w01 + f10.x * w10 + f11.x * w11;
                o.y = f00.y * w00 + f01.y * w01 + f10.y * w10 + f11.y * w11;
                o.x = __uint_as_float(f2tf32(o.x));
                o.y = __uint_as_float(f2tf32(o.y));
                *(float2*)(srow + half * 8 + 2 * j) = o;
            }
        }
        __syncthreads();

        const int hw = h * 7 + w;
        #pragma unroll
        for (int it = 0; it < 4; ++it) {
            const int u = tid + it * 256;       // slot 0..1023
            const int cc = u >> 7, rem = u & 127;
            const int ks = rem >> 5, ln = rem & 31;
            const int gg = ln >> 2, tg = ln & 3;
            const int ch = cc * 32 + ks * 8 + tg;
            uint4 wv;
            wv.x = __float_as_uint(s[gg * 258 + ch]);
            wv.y = __float_as_uint(s[(gg + 8) * 258 + ch]);
            wv.z = __float_as_uint(s[gg * 258 + ch + 4]);
            wv.w = __float_as_uint(s[(gg + 8) * 258 + ch + 4]);
            *(uint4*)(outb + (size_t)(hw * 8 + cc) * TILE_BYTES + rem * 16) = wv;
        }
        __syncthreads();
    }
}

// ================= generic tf32 MMA GEMM: 128x128x32, 4-stage cp.async =========
#define NSTAGE 4
#define STAGE_BYTES 32768
#define SM_TOTAL (NSTAGE * STAGE_BYTES)

__device__ __forceinline__ void cp16(void* smem_dst, const void* gmem_src) {
    unsigned s = (unsigned)__cvta_generic_to_shared(smem_dst);
    asm volatile("cp.async.cg.shared.global [%0], [%1], 16;" :: "r"(s), "l"(gmem_src));
}
__device__ __forceinline__ void cp_commit() { asm volatile("cp.async.commit_group;"); }
template<int N> __device__ __forceinline__ void cp_wait() {
    asm volatile("cp.async.wait_group %0;" :: "n"(N));
}

// outFrag != 0: BN+ReLU then emit A-fragment tiles (for next GEMM)
// outMax  != 0: BN+ReLU then max over 8-row groups -> out[node][col]
__global__ void __launch_bounds__(256, 1)
gemm_tc(const char* __restrict__ Afrag, const char* __restrict__ Bfrag, int nchunk,
        char* __restrict__ outFrag, float* __restrict__ outMax,
        const float* __restrict__ bias, const float* __restrict__ gamma,
        const float* __restrict__ beta, const float* __restrict__ mean,
        const float* __restrict__ var)
{
    extern __shared__ char sm[];
    const int tid = threadIdx.x, lane = tid & 31, wid = tid >> 5;
    const int warp_m = wid >> 1, warp_n = wid & 1;
    const int ntile = blockIdx.x, mtile = blockIdx.y;

    const char* Ag = Afrag + (size_t)mtile * nchunk * TILE_BYTES;
    const char* Bg = Bfrag + (size_t)ntile * nchunk * TILE_BYTES;

    float acc[2][8][4];
    #pragma unroll
    for (int mt = 0; mt < 2; ++mt)
        #pragma unroll
        for (int nt = 0; nt < 8; ++nt)
            #pragma unroll
            for (int j = 0; j < 4; ++j) acc[mt][nt][j] = 0.f;

    #pragma unroll
    for (int t = 0; t < 3; ++t) {
        char* sa = sm + t * STAGE_BYTES;
        #pragma unroll
        for (int i = 0; i < 4; ++i) {
            const int off = (tid + i * 256) * 16;
            cp16(sa + off,         Ag + (size_t)t * TILE_BYTES + off);
            cp16(sa + 16384 + off, Bg + (size_t)t * TILE_BYTES + off);
        }
        cp_commit();
    }

    const int aBase = (warp_m * 2) * 2048 + lane * 16;
    const int bBase = 16384 + (warp_n * 8) * 1024 + lane * 16;

    for (int t = 0; t < nchunk; ++t) {
        cp_wait<2>();
        __syncthreads();

        if (t + 3 < nchunk) {
            char* sa = sm + ((t + 3) & 3) * STAGE_BYTES;
            #pragma unroll
            for (int i = 0; i < 4; ++i) {
                const int off = (tid + i * 256) * 16;
                cp16(sa + off,         Ag + (size_t)(t + 3) * TILE_BYTES + off);
                cp16(sa + 16384 + off, Bg + (size_t)(t + 3) * TILE_BYTES + off);
            }
        }
        cp_commit();

        const char* S = sm + (t & 3) * STAGE_BYTES;
        #pragma unroll
        for (int kp = 0; kp < 2; ++kp) {
            uint4 bf[8];
            #pragma unroll
            for (int nt = 0; nt < 8; ++nt)
                bf[nt] = *(const uint4*)(S + bBase + nt * 1024 + kp * 512);
            #pragma unroll
            for (int ksh = 0; ksh < 2; ++ksh) {
                const int ks = kp * 2 + ksh;
                uint4 af[2];
                #pragma unroll
                for (int mt = 0; mt < 2; ++mt)
                    af[mt] = *(const uint4*)(S + aBase + mt * 2048 + ks * 512);
                #pragma unroll
                for (int nt = 0; nt < 8; ++nt) {
                    const uint32_t b0 = ksh ? bf[nt].z : bf[nt].x;
                    const uint32_t b1 = ksh ? bf[nt].w : bf[nt].y;
                    #pragma unroll
                    for (int mt = 0; mt < 2; ++mt) {
                        asm volatile(
                            "mma.sync.aligned.m16n8k8.row.col.f32.tf32.tf32.f32 "
                            "{%0,%1,%2,%3}, {%4,%5,%6,%7}, {%8,%9}, {%0,%1,%2,%3};"
                            : "+f"(acc[mt][nt][0]), "+f"(acc[mt][nt][1]),
                              "+f"(acc[mt][nt][2]), "+f"(acc[mt][nt][3])
                            : "r"(af[mt].x), "r"(af[mt].y), "r"(af[mt].z), "r"(af[mt].w),
                              "r"(b0), "r"(b1));
                    }
                }
            }
        }
    }

    const int g = lane >> 2, tg = lane & 3;

    if (outFrag) {
        // stage BN+ReLU tile in smem, then emit A-fragment-order tf32 tiles
        __syncthreads();
        float* st = (float*)sm;   // 128 x 132
        #pragma unroll
        for (int nt = 0; nt < 8; ++nt) {
            const int c0l = warp_n * 64 + nt * 8 + tg * 2;
            const int cg0 = ntile * 128 + c0l;
            const float s0 = gamma[cg0]     * rsqrtf(var[cg0]     + EPS);
            const float s1 = gamma[cg0 + 1] * rsqrtf(var[cg0 + 1] + EPS);
            const float h0  = (bias[cg0]     - mean[cg0])     * s0 + beta[cg0];
            const float h1v = (bias[cg0 + 1] - mean[cg0 + 1]) * s1 + beta[cg0 + 1];
            #pragma unroll
            for (int mt = 0; mt < 2; ++mt) {
                const int rowl = warp_m * 32 + mt * 16 + g;
                float2 v;
                v.x = fmaxf(acc[mt][nt][0] * s0 + h0,  0.f);
                v.y = fmaxf(acc[mt][nt][1] * s1 + h1v, 0.f);
                *(float2*)&st[rowl * 132 + c0l] = v;
                v.x = fmaxf(acc[mt][nt][2] * s0 + h0,  0.f);
                v.y = fmaxf(acc[mt][nt][3] * s1 + h1v, 0.f);
                *(float2*)&st[(rowl + 8) * 132 + c0l] = v;
            }
        }
        __syncthreads();
        char* dst = outFrag + (size_t)(mtile * (gridDim.x * 4) + ntile * 4) * TILE_BYTES;
        #pragma unroll
        for (int it = 0; it < 16; ++it) {
            const int u = tid + it * 256;        // 0..4095
            const int cc = u >> 10, rem = u & 1023;
            const int sub = rem >> 7, r2 = rem & 127;
            const int ks = r2 >> 5, ln = r2 & 31;
            const int gg = ln >> 2, tg2 = ln & 3;
            const int row = sub * 16 + gg;
            const int k = cc * 32 + ks * 8 + tg2;
            uint4 wv;
            wv.x = f2tf32(st[row * 132 + k]);
            wv.y = f2tf32(st[(row + 8) * 132 + k]);
            wv.z = f2tf32(st[row * 132 + k + 4]);
            wv.w = f2tf32(st[(row + 8) * 132 + k + 4]);
            *(uint4*)(dst + (size_t)cc * TILE_BYTES + rem * 16) = wv;
        }
    } else {
        // fused BN + ReLU + max over 8-row groups -> outMax[node][col]
        const int n0 = ntile * 128 + warp_n * 64;
        #pragma unroll
        for (int nt = 0; nt < 8; ++nt) {
            const int c0 = n0 + nt * 8 + tg * 2;
            const float s0 = gamma[c0]     * rsqrtf(var[c0]     + EPS);
            const float s1 = gamma[c0 + 1] * rsqrtf(var[c0 + 1] + EPS);
            const float h0  = (bias[c0]     - mean[c0])     * s0 + beta[c0];
            const float h1v = (bias[c0 + 1] - mean[c0 + 1]) * s1 + beta[c0 + 1];
            #pragma unroll
            for (int mt = 0; mt < 2; ++mt) {
                float v0 = fmaxf(acc[mt][nt][0] * s0 + h0,  0.f);   // row base+g
                float v1 = fmaxf(acc[mt][nt][1] * s1 + h1v, 0.f);
                float v2 = fmaxf(acc[mt][nt][2] * s0 + h0,  0.f);   // row base+8+g
                float v3 = fmaxf(acc[mt][nt][3] * s1 + h1v, 0.f);
                #pragma unroll
                for (int d = 4; d <= 16; d <<= 1) {
                    v0 = fmaxf(v0, __shfl_xor_sync(0xffffffffu, v0, d));
                    v1 = fmaxf(v1, __shfl_xor_sync(0xffffffffu, v1, d));
                    v2 = fmaxf(v2, __shfl_xor_sync(0xffffffffu, v2, d));
                    v3 = fmaxf(v3, __shfl_xor_sync(0xffffffffu, v3, d));
                }
                if (lane < 4) {
                    const int node0 = mtile * 16 + warp_m * 4 + mt * 2;
                    float2 a; a.x = v0; a.y = v1;
                    float2 b; b.x = v2; b.y = v3;
                    *(float2*)&outMax[(size_t)node0 * DD + c0] = a;
                    *(float2*)&outMax[(size_t)(node0 + 1) * DD + c0] = b;
                }
            }
        }
    }
}

// ---------------- launch ----------------
extern "C" void kernel_launch(void* const* d_in, const int* in_sizes, int n_in,
                              void* d_out, int out_size)
{
    const float* images = (const float*)d_in[0];
    const int*   kf     = (const int*)  d_in[1];
    const float* boxes  = (const float*)d_in[2];
    const float* w1     = (const float*)d_in[3];
    const float* b1     = (const float*)d_in[4];
    const float* g1     = (const float*)d_in[5];
    const float* bt1    = (const float*)d_in[6];
    const float* m1     = (const float*)d_in[7];
    const float* v1     = (const float*)d_in[8];
    const float* w2     = (const float*)d_in[9];
    const float* b2     = (const float*)d_in[10];
    const float* g2     = (const float*)d_in[11];
    const float* bt2    = (const float*)d_in[12];
    const float* m2     = (const float*)d_in[13];
    const float* v2     = (const float*)d_in[14];
    float* out = (float*)d_out;

    char *roiT, *w1tT, *h1T, *w2T;
    cudaGetSymbolAddress((void**)&roiT, g_roiT);
    cudaGetSymbolAddress((void**)&w1tT, g_w1tT);
    cudaGetSymbolAddress((void**)&h1T,  g_h1T);
    cudaGetSymbolAddress((void**)&w2T,  g_w2T);

    cudaFuncSetAttribute(gemm_tc, cudaFuncAttributeMaxDynamicSharedMemorySize, SM_TOTAL);

    transpose_img<<<dim3(NPIX / 32, CCH / 64, NF), dim3(32, 8)>>>(images);
    transpose_w1<<<HID, 256>>>(w1);
    repack_w2<<<DD, 128>>>(w2);
    roi_gather_frag<<<dim3(256, 7), 256>>>(kf, boxes);
    gemm_tc<<<dim3(4, 32), 256, SM_TOTAL>>>(
        roiT, w1tT, NCHUNK, h1T, nullptr, b1, g1, bt1, m1, v1);
    gemm_tc<<<dim3(4, 32), 256, SM_TOTAL>>>(
        h1T, w2T, 16, nullptr, out, b2, g2, bt2, m2, v2);
}

// round 6
// speedup vs baseline: 4.5465x; 1.3931x over previous
#include <cuda_runtime.h>
#include <cuda_fp16.h>
#include <cstdint>

#define EPS 0.001f
#define NF   64
#define CCH  256
#define NPIX 1600        // 40*40
#define RTOT 4096        // N*K = 512*8
#define K1   12544       // 49*256
#define HID  512
#define DD   512
#define NCHUNK 392       // K1/32
#define TILE_BYTES 8192  // 128 rows x 32 k (fp16), fragment order
#define TILE_HALVES 4096

// ---- scratch (static __device__ per allocation rules) ----
__device__ __half g_imgH[(size_t)NF * NPIX * CCH];            // NHWC fp16 images (52 MB)
__device__ __half g_w1tT[(size_t)4 * NCHUNK * TILE_HALVES];   // B1 frag tiles
__device__ __half g_roiT[(size_t)32 * NCHUNK * TILE_HALVES];  // A1 frag tiles (103 MB)
__device__ __half g_h1T [(size_t)32 * 16 * TILE_HALVES];      // h1 as A2 frag tiles
__device__ __half g_w2T [(size_t)4 * 16 * TILE_HALVES];       // B2 frag tiles

// ---------------- image transpose NCHW f32 -> NHWC f16 ----------------
__global__ void transpose_img(const float* __restrict__ in)
{
    __shared__ float s[64][33];
    const int f  = blockIdx.z;
    const float* src = in + (size_t)f * CCH * NPIX;
    const int p0 = blockIdx.x * 32;
    const int c0 = blockIdx.y * 64;
    #pragma unroll
    for (int i = threadIdx.y; i < 64; i += 8)
        s[i][threadIdx.x] = src[(size_t)(c0 + i) * NPIX + p0 + threadIdx.x];
    __syncthreads();
    __half2* dst = (__half2*)g_imgH + (size_t)f * NPIX * 128 + (c0 >> 1) + threadIdx.x;
    #pragma unroll
    for (int i = threadIdx.y; i < 32; i += 8)
        dst[(size_t)(p0 + i) * 128] =
            __floats2half2_rn(s[2 * threadIdx.x][i], s[2 * threadIdx.x + 1][i]);
}

// ---------------- w1 -> fp16 B-fragment tiles ----------------
// B[n=o][k], k = hw*256 + c (c fastest); source w1[o][c*49+hw]
// B slot (nsub, ks, ln=gcol*4+tg), 8B: [0:4)=b0 (k=2tg,2tg+1), [4:8)=b1 (k+8,k+9)
__global__ void transpose_w1(const float* __restrict__ w1)
{
    const int o = blockIdx.x;
    const int ntile = o >> 7, col = o & 127;
    const int nsub = col >> 3, gcol = col & 7;
    const float* src = w1 + (size_t)o * K1;
    for (int k2 = threadIdx.x; k2 < K1 / 2; k2 += blockDim.x) {
        const int k = k2 * 2;
        const int hw = k >> 8, c = k & 255;
        const float v0 = __ldg(&src[c * 49 + hw]);
        const float v1 = __ldg(&src[(c + 1) * 49 + hw]);
        const int chunk = k >> 5, kk = k & 31;
        const int ks = kk >> 4, kkk = kk & 15;
        const int tg = (kkk & 7) >> 1;
        const uint32_t off = nsub * 512 + ks * 256 + (gcol * 4 + tg) * 8 + ((kkk >= 8) ? 4 : 0);
        *(__half2*)((char*)g_w1tT + (size_t)(ntile * NCHUNK + chunk) * TILE_BYTES + off) =
            __floats2half2_rn(v0, v1);
    }
}

// ---------------- w2 -> fp16 B-fragment tiles ----------------
__global__ void repack_w2(const float* __restrict__ w2)
{
    const int o = blockIdx.x;
    const int ntile = o >> 7, col = o & 127;
    const int nsub = col >> 3, gcol = col & 7;
    for (int k2 = threadIdx.x; k2 < DD / 2; k2 += blockDim.x) {
        const int k = k2 * 2;
        const float v0 = __ldg(&w2[(size_t)o * DD + k]);
        const float v1 = __ldg(&w2[(size_t)o * DD + k + 1]);
        const int chunk = k >> 5, kk = k & 31;
        const int ks = kk >> 4, kkk = kk & 15;
        const int tg = (kkk & 7) >> 1;
        const uint32_t off = nsub * 512 + ks * 256 + (gcol * 4 + tg) * 8 + ((kkk >= 8) ? 4 : 0);
        *(__half2*)((char*)g_w2T + (size_t)(ntile * 16 + chunk) * TILE_BYTES + off) =
            __floats2half2_rn(v0, v1);
    }
}

// ---------------- fused RoIAlign gather -> fp16 A fragment tiles (h-split) ----------------
// grid (256 roi-groups, 7 h); block 256: rl = tid&15 (roi), cg = tid>>4 (16 channels)
// A slot (sub, ks, ln=g*4+tg), 16B: a0=(row g, k=2tg,2tg+1) a1=(row g+8) a2=(g, k+8,9) a3=(g+8)
union U4 { uint4 u; __half2 h[4]; };

__global__ void __launch_bounds__(256) roi_gather_frag(const int* __restrict__ kf,
                                                       const float* __restrict__ boxes)
{
    __shared__ char s[8192];
    const int blk = blockIdx.x;                  // 0..255
    const int h   = blockIdx.y;                  // 0..6
    const int mtile = blk >> 3, sub = blk & 7;
    const int tid = threadIdx.x;
    const int rl = tid & 15, cg = tid >> 4;
    const int r = blk * 16 + rl;
    const int f = kf[r];
    const float x1 = boxes[r * 4 + 0] * 40.f;
    const float y1 = boxes[r * 4 + 1] * 40.f;
    const float x2 = boxes[r * 4 + 2] * 40.f;
    const float y2 = boxes[r * 4 + 3] * 40.f;
    const float bw = (x2 - x1) * (1.f / 7.f);
    const float bh = (y2 - y1) * (1.f / 7.f);

    const uint4* img = (const uint4*)(g_imgH + (size_t)f * NPIX * CCH);
    char* outb = (char*)g_roiT + (size_t)mtile * NCHUNK * TILE_BYTES + sub * 1024;

    const float Y = y1 + (h + 0.5f) * bh;
    const float yc = fminf(fmaxf(Y, 0.f), 39.f);
    const int   y0 = (int)yc;
    const int   y1i = min(y0 + 1, 39);
    const float ly = yc - (float)y0;

    // per-thread smem address bases for the 8 half2 words (j = 0..7)
    const int g = rl & 7, hi = rl >> 3;

    for (int w = 0; w < 7; ++w) {
        const float X = x1 + (w + 0.5f) * bw;
        const bool valid = (X > -1.f) && (X < 40.f) && (Y > -1.f) && (Y < 40.f);
        const float xc = fminf(fmaxf(X, 0.f), 39.f);
        const int   x0 = (int)xc;
        const int   x1i = min(x0 + 1, 39);
        const float lx = xc - (float)x0;
        float w00 = (1.f - ly) * (1.f - lx);
        float w01 = (1.f - ly) * lx;
        float w10 = ly * (1.f - lx);
        float w11 = ly * lx;
        if (!valid) { w00 = w01 = w10 = w11 = 0.f; }

        const uint4* q00 = img + (y0  * 40 + x0 ) * 32 + cg * 2;
        const uint4* q01 = img + (y0  * 40 + x1i) * 32 + cg * 2;
        const uint4* q10 = img + (y1i * 40 + x0 ) * 32 + cg * 2;
        const uint4* q11 = img + (y1i * 40 + x1i) * 32 + cg * 2;

        #pragma unroll
        for (int half = 0; half < 2; ++half) {
            U4 c00, c01, c10, c11;
            c00.u = q00[half]; c01.u = q01[half];
            c10.u = q10[half]; c11.u = q11[half];
            #pragma unroll
            for (int jj = 0; jj < 4; ++jj) {
                const int j = half * 4 + jj;
                const float2 f00 = __half22float2(c00.h[jj]);
                const float2 f01 = __half22float2(c01.h[jj]);
                const float2 f10 = __half22float2(c10.h[jj]);
                const float2 f11 = __half22float2(c11.h[jj]);
                float ox = f00.x * w00 + f01.x * w01 + f10.x * w10 + f11.x * w11;
                float oy = f00.y * w00 + f01.y * w01 + f10.y * w10 + f11.y * w11;
                // channel pair c = cg*16 + 2j
                const int c = cg * 16 + 2 * j;
                const int cc = c >> 5, r5 = c & 31;
                const int ks = r5 >> 4, kkk = r5 & 15;
                const int tg = (kkk & 7) >> 1;
                const uint32_t addr = cc * 1024 + ks * 512 + (g * 4 + tg) * 16
                                    + ((kkk >= 8) ? 8 : 0) + hi * 4;
                *(__half2*)(s + addr) = __floats2half2_rn(ox, oy);
            }
        }
        __syncthreads();

        const int hw = h * 7 + w;
        #pragma unroll
        for (int it = 0; it < 2; ++it) {
            const int u = tid + it * 256;       // slot 0..511
            const int cc = u >> 6, rem = u & 63;
            const uint4 wv = *(const uint4*)(s + u * 16);
            *(uint4*)(outb + (size_t)(hw * 8 + cc) * TILE_BYTES + rem * 16) = wv;
        }
        __syncthreads();
    }
}

// ================= generic fp16 MMA GEMM: 128x128x32, 4-stage cp.async =========
#define NSTAGE 4
#define STAGE_BYTES 16384
#define SM_TOTAL (NSTAGE * STAGE_BYTES)

__device__ __forceinline__ void cp16(void* smem_dst, const void* gmem_src) {
    unsigned s = (unsigned)__cvta_generic_to_shared(smem_dst);
    asm volatile("cp.async.cg.shared.global [%0], [%1], 16;" :: "r"(s), "l"(gmem_src));
}
__device__ __forceinline__ void cp_commit() { asm volatile("cp.async.commit_group;"); }
template<int N> __device__ __forceinline__ void cp_wait() {
    asm volatile("cp.async.wait_group %0;" :: "n"(N));
}

// outFrag != 0: BN+ReLU then emit fp16 A-fragment tiles (for next GEMM)
// else:         BN+ReLU then max over 8-row groups -> outMax[node][col]
__global__ void __launch_bounds__(256, 1)
gemm_tc(const char* __restrict__ Afrag, const char* __restrict__ Bfrag, int nchunk,
        char* __restrict__ outFrag, float* __restrict__ outMax,
        const float* __restrict__ bias, const float* __restrict__ gamma,
        const float* __restrict__ beta, const float* __restrict__ mean,
        const float* __restrict__ var)
{
    extern __shared__ char sm[];
    const int tid = threadIdx.x, lane = tid & 31, wid = tid >> 5;
    const int warp_m = wid >> 1, warp_n = wid & 1;
    const int ntile = blockIdx.x, mtile = blockIdx.y;

    const char* Ag = Afrag + (size_t)mtile * nchunk * TILE_BYTES;
    const char* Bg = Bfrag + (size_t)ntile * nchunk * TILE_BYTES;

    float acc[2][8][4];
    #pragma unroll
    for (int mt = 0; mt < 2; ++mt)
        #pragma unroll
        for (int nt = 0; nt < 8; ++nt)
            #pragma unroll
            for (int j = 0; j < 4; ++j) acc[mt][nt][j] = 0.f;

    #pragma unroll
    for (int t = 0; t < 3; ++t) {
        char* sa = sm + t * STAGE_BYTES;
        #pragma unroll
        for (int i = 0; i < 2; ++i) {
            const int off = (tid + i * 256) * 16;
            cp16(sa + off,        Ag + (size_t)t * TILE_BYTES + off);
            cp16(sa + 8192 + off, Bg + (size_t)t * TILE_BYTES + off);
        }
        cp_commit();
    }

    const int aBase = (warp_m * 2) * 1024 + lane * 16;
    const int bBase = 8192 + (warp_n * 8) * 512 + lane * 8;

    for (int t = 0; t < nchunk; ++t) {
        cp_wait<2>();
        __syncthreads();

        if (t + 3 < nchunk) {
            char* sa = sm + ((t + 3) & 3) * STAGE_BYTES;
            #pragma unroll
            for (int i = 0; i < 2; ++i) {
                const int off = (tid + i * 256) * 16;
                cp16(sa + off,        Ag + (size_t)(t + 3) * TILE_BYTES + off);
                cp16(sa + 8192 + off, Bg + (size_t)(t + 3) * TILE_BYTES + off);
            }
        }
        cp_commit();

        const char* S = sm + (t & 3) * STAGE_BYTES;
        #pragma unroll
        for (int ks = 0; ks < 2; ++ks) {
            uint2 bf[8];
            #pragma unroll
            for (int nt = 0; nt < 8; ++nt)
                bf[nt] = *(const uint2*)(S + bBase + nt * 512 + ks * 256);
            uint4 af[2];
            #pragma unroll
            for (int mt = 0; mt < 2; ++mt)
                af[mt] = *(const uint4*)(S + aBase + mt * 1024 + ks * 512);
            #pragma unroll
            for (int nt = 0; nt < 8; ++nt) {
                #pragma unroll
                for (int mt = 0; mt < 2; ++mt) {
                    asm volatile(
                        "mma.sync.aligned.m16n8k16.row.col.f32.f16.f16.f32 "
                        "{%0,%1,%2,%3}, {%4,%5,%6,%7}, {%8,%9}, {%0,%1,%2,%3};"
                        : "+f"(acc[mt][nt][0]), "+f"(acc[mt][nt][1]),
                          "+f"(acc[mt][nt][2]), "+f"(acc[mt][nt][3])
                        : "r"(af[mt].x), "r"(af[mt].y), "r"(af[mt].z), "r"(af[mt].w),
                          "r"(bf[nt].x), "r"(bf[nt].y));
                }
            }
        }
    }

    const int g = lane >> 2, tg = lane & 3;

    if (outFrag) {
        // stage BN+ReLU tile in smem as half2 (stride 66), then emit A-frag fp16 tiles
        __syncthreads();
        __half2* st2 = (__half2*)sm;
        #pragma unroll
        for (int nt = 0; nt < 8; ++nt) {
            const int c0l = warp_n * 64 + nt * 8 + tg * 2;
            const int cg0 = ntile * 128 + c0l;
            const float s0 = gamma[cg0]     * rsqrtf(var[cg0]     + EPS);
            const float s1 = gamma[cg0 + 1] * rsqrtf(var[cg0 + 1] + EPS);
            const float h0  = (bias[cg0]     - mean[cg0])     * s0 + beta[cg0];
            const float h1v = (bias[cg0 + 1] - mean[cg0 + 1]) * s1 + beta[cg0 + 1];
            #pragma unroll
            for (int mt = 0; mt < 2; ++mt) {
                const int rowl = warp_m * 32 + mt * 16 + g;
                st2[rowl * 66 + (c0l >> 1)] = __floats2half2_rn(
                    fmaxf(acc[mt][nt][0] * s0 + h0,  0.f),
                    fmaxf(acc[mt][nt][1] * s1 + h1v, 0.f));
                st2[(rowl + 8) * 66 + (c0l >> 1)] = __floats2half2_rn(
                    fmaxf(acc[mt][nt][2] * s0 + h0,  0.f),
                    fmaxf(acc[mt][nt][3] * s1 + h1v, 0.f));
            }
        }
        __syncthreads();
        char* dst = outFrag + (size_t)(mtile * 16 + ntile * 4) * TILE_BYTES;
        #pragma unroll
        for (int it = 0; it < 8; ++it) {
            const int u = tid + it * 256;        // 0..2047 (16B slots)
            const int chunkl = u >> 9, sidx = u & 511;
            const int subr = sidx >> 6, rem = sidx & 63;
            const int ks2 = rem >> 5, ln = rem & 31;
            const int g2 = ln >> 2, tg2 = ln & 3;
            const int row = subr * 16 + g2;
            const int kp = chunkl * 16 + ks2 * 8 + tg2;
            uint4 wv;
            wv.x = *(const uint32_t*)&st2[row * 66 + kp];
            wv.y = *(const uint32_t*)&st2[(row + 8) * 66 + kp];
            wv.z = *(const uint32_t*)&st2[row * 66 + kp + 4];
            wv.w = *(const uint32_t*)&st2[(row + 8) * 66 + kp + 4];
            *(uint4*)(dst + (size_t)chunkl * TILE_BYTES + subr * 1024 + rem * 16) = wv;
        }
    } else {
        // fused BN + ReLU + max over 8-row groups -> outMax[node][col]
        const int n0 = ntile * 128 + warp_n * 64;
        #pragma unroll
        for (int nt = 0; nt < 8; ++nt) {
            const int c0 = n0 + nt * 8 + tg * 2;
            const float s0 = gamma[c0]     * rsqrtf(var[c0]     + EPS);
            const float s1 = gamma[c0 + 1] * rsqrtf(var[c0 + 1] + EPS);
            const float h0  = (bias[c0]     - mean[c0])     * s0 + beta[c0];
            const float h1v = (bias[c0 + 1] - mean[c0 + 1]) * s1 + beta[c0 + 1];
            #pragma unroll
            for (int mt = 0; mt < 2; ++mt) {
                float v0 = fmaxf(acc[mt][nt][0] * s0 + h0,  0.f);
                float v1 = fmaxf(acc[mt][nt][1] * s1 + h1v, 0.f);
                float v2 = fmaxf(acc[mt][nt][2] * s0 + h0,  0.f);
                float v3 = fmaxf(acc[mt][nt][3] * s1 + h1v, 0.f);
                #pragma unroll
                for (int d = 4; d <= 16; d <<= 1) {
                    v0 = fmaxf(v0, __shfl_xor_sync(0xffffffffu, v0, d));
                    v1 = fmaxf(v1, __shfl_xor_sync(0xffffffffu, v1, d));
                    v2 = fmaxf(v2, __shfl_xor_sync(0xffffffffu, v2, d));
                    v3 = fmaxf(v3, __shfl_xor_sync(0xffffffffu, v3, d));
                }
                if (lane < 4) {
                    const int node0 = mtile * 16 + warp_m * 4 + mt * 2;
                    float2 a; a.x = v0; a.y = v1;
                    float2 b; b.x = v2; b.y = v3;
                    *(float2*)&outMax[(size_t)node0 * DD + c0] = a;
                    *(float2*)&outMax[(size_t)(node0 + 1) * DD + c0] = b;
                }
            }
        }
    }
}

// ---------------- launch ----------------
extern "C" void kernel_launch(void* const* d_in, const int* in_sizes, int n_in,
                              void* d_out, int out_size)
{
    const float* images = (const float*)d_in[0];
    const int*   kf     = (const int*)  d_in[1];
    const float* boxes  = (const float*)d_in[2];
    const float* w1     = (const float*)d_in[3];
    const float* b1     = (const float*)d_in[4];
    const float* g1     = (const float*)d_in[5];
    const float* bt1    = (const float*)d_in[6];
    const float* m1     = (const float*)d_in[7];
    const float* v1     = (const float*)d_in[8];
    const float* w2     = (const float*)d_in[9];
    const float* b2     = (const float*)d_in[10];
    const float* g2     = (const float*)d_in[11];
    const float* bt2    = (const float*)d_in[12];
    const float* m2     = (const float*)d_in[13];
    const float* v2     = (const float*)d_in[14];
    float* out = (float*)d_out;

    char *roiT, *w1tT, *h1T, *w2T;
    cudaGetSymbolAddress((void**)&roiT, g_roiT);
    cudaGetSymbolAddress((void**)&w1tT, g_w1tT);
    cudaGetSymbolAddress((void**)&h1T,  g_h1T);
    cudaGetSymbolAddress((void**)&w2T,  g_w2T);

    cudaFuncSetAttribute(gemm_tc, cudaFuncAttributeMaxDynamicSharedMemorySize, SM_TOTAL);

    transpose_img<<<dim3(NPIX / 32, CCH / 64, NF), dim3(32, 8)>>>(images);
    transpose_w1<<<HID, 256>>>(w1);
    repack_w2<<<DD, 128>>>(w2);
    roi_gather_frag<<<dim3(256, 7), 256>>>(kf, boxes);
    gemm_tc<<<dim3(4, 32), 256, SM_TOTAL>>>(
        roiT, w1tT, NCHUNK, h1T, nullptr, b1, g1, bt1, m1, v1);
    gemm_tc<<<dim3(4, 32), 256, SM_TOTAL>>>(
        h1T, w2T, 16, nullptr, out, b2, g2, bt2, m2, v2);
}

// round 7
// speedup vs baseline: 5.6433x; 1.2413x over previous
#include <cuda_runtime.h>
#include <cuda_fp16.h>
#include <cstdint>

#define EPS 0.001f
#define NF   64
#define CCH  256
#define NPIX 1600        // 40*40
#define RTOT 4096        // N*K = 512*8
#define HID  512
#define DD   512
#define K1   12544       // 49*256
#define NCHUNK 392       // K1/32
#define TILE_BYTES 8192  // 128 rows x 32 k (fp16), fragment order
#define TILE_HALVES 4096

// ---- scratch (static __device__ per allocation rules) ----
__device__ __half g_imgH[(size_t)NF * NPIX * CCH];            // NHWC fp16 images (52 MB)
__device__ __half g_w1tT[(size_t)4 * NCHUNK * TILE_HALVES];   // B1 frag tiles
__device__ __half g_roiT[(size_t)32 * NCHUNK * TILE_HALVES];  // A1 frag tiles (103 MB)
__device__ __half g_h1T [(size_t)32 * 16 * TILE_HALVES];      // h1 as A2 frag tiles
__device__ __half g_w2T [(size_t)4 * 16 * TILE_HALVES];       // B2 frag tiles

// ---------------- image transpose NCHW f32 -> NHWC f16 ----------------
__global__ void transpose_img(const float* __restrict__ in)
{
    __shared__ float s[64][33];
    const int f  = blockIdx.z;
    const float* src = in + (size_t)f * CCH * NPIX;
    const int p0 = blockIdx.x * 32;
    const int c0 = blockIdx.y * 64;
    #pragma unroll
    for (int i = threadIdx.y; i < 64; i += 8)
        s[i][threadIdx.x] = src[(size_t)(c0 + i) * NPIX + p0 + threadIdx.x];
    __syncthreads();
    __half2* dst = (__half2*)g_imgH + (size_t)f * NPIX * 128 + (c0 >> 1) + threadIdx.x;
    #pragma unroll
    for (int i = threadIdx.y; i < 32; i += 8)
        dst[(size_t)(p0 + i) * 128] =
            __floats2half2_rn(s[2 * threadIdx.x][i], s[2 * threadIdx.x + 1][i]);
}

// ---------------- w1 -> fp16 B-fragment tiles ----------------
// B[n=o][k], k = hw*256 + c (c fastest); source w1[o][c*49+hw]
__global__ void transpose_w1(const float* __restrict__ w1)
{
    const int o = blockIdx.x;
    const int ntile = o >> 7, col = o & 127;
    const int nsub = col >> 3, gcol = col & 7;
    const float* src = w1 + (size_t)o * K1;
    for (int k2 = threadIdx.x; k2 < K1 / 2; k2 += blockDim.x) {
        const int k = k2 * 2;
        const int hw = k >> 8, c = k & 255;
        const float v0 = __ldg(&src[c * 49 + hw]);
        const float v1 = __ldg(&src[(c + 1) * 49 + hw]);
        const int chunk = k >> 5, kk = k & 31;
        const int ks = kk >> 4, kkk = kk & 15;
        const int tg = (kkk & 7) >> 1;
        const uint32_t off = nsub * 512 + ks * 256 + (gcol * 4 + tg) * 8 + ((kkk >= 8) ? 4 : 0);
        *(__half2*)((char*)g_w1tT + (size_t)(ntile * NCHUNK + chunk) * TILE_BYTES + off) =
            __floats2half2_rn(v0, v1);
    }
}

// ---------------- w2 -> fp16 B-fragment tiles ----------------
__global__ void repack_w2(const float* __restrict__ w2)
{
    const int o = blockIdx.x;
    const int ntile = o >> 7, col = o & 127;
    const int nsub = col >> 3, gcol = col & 7;
    for (int k2 = threadIdx.x; k2 < DD / 2; k2 += blockDim.x) {
        const int k = k2 * 2;
        const float v0 = __ldg(&w2[(size_t)o * DD + k]);
        const float v1 = __ldg(&w2[(size_t)o * DD + k + 1]);
        const int chunk = k >> 5, kk = k & 31;
        const int ks = kk >> 4, kkk = kk & 15;
        const int tg = (kkk & 7) >> 1;
        const uint32_t off = nsub * 512 + ks * 256 + (gcol * 4 + tg) * 8 + ((kkk >= 8) ? 4 : 0);
        *(__half2*)((char*)g_w2T + (size_t)(ntile * 16 + chunk) * TILE_BYTES + off) =
            __floats2half2_rn(v0, v1);
    }
}

// ---------------- fused RoIAlign gather -> fp16 A fragment tiles ----------------
// grid (256 roi-groups, 7 h); block 256 = 8 warps.
// Warp wp owns rois blk*16+wp and blk*16+wp+8; lane covers 16B (8 channels) of a pixel.
// Staging (warp-private rows): phys word = t ^ (bit5(t)<<2)  (conflict-free write+read)
union U4 { uint4 u; __half2 h[4]; };

__global__ void __launch_bounds__(256) roi_gather_frag(const int* __restrict__ kf,
                                                       const float* __restrict__ boxes)
{
    __shared__ uint32_t s[16 * 132];              // 16 rows x 132 words (+4-word row skew)
    const int blk = blockIdx.x;                   // 0..255
    const int h   = blockIdx.y;                   // 0..6
    const int mtile = blk >> 3, sub = blk & 7;
    const int tid = threadIdx.x, lane = tid & 31, wp = tid >> 5;
    const int rA = blk * 16 + wp, rB = rA + 8;

    const int fA = kf[rA], fB = kf[rB];
    const float ax1 = boxes[rA * 4 + 0] * 40.f, ay1 = boxes[rA * 4 + 1] * 40.f;
    const float ax2 = boxes[rA * 4 + 2] * 40.f, ay2 = boxes[rA * 4 + 3] * 40.f;
    const float bx1 = boxes[rB * 4 + 0] * 40.f, by1 = boxes[rB * 4 + 1] * 40.f;
    const float bx2 = boxes[rB * 4 + 2] * 40.f, by2 = boxes[rB * 4 + 3] * 40.f;
    const float abw = (ax2 - ax1) * (1.f / 7.f), abh = (ay2 - ay1) * (1.f / 7.f);
    const float bbw = (bx2 - bx1) * (1.f / 7.f), bbh = (by2 - by1) * (1.f / 7.f);

    const uint4* imgA = (const uint4*)(g_imgH + (size_t)fA * NPIX * CCH);
    const uint4* imgB = (const uint4*)(g_imgH + (size_t)fB * NPIX * CCH);
    char* outb = (char*)g_roiT + (size_t)mtile * NCHUNK * TILE_BYTES + sub * 1024;

    // y geometry (per roi, fixed for this h)
    const float YA = ay1 + (h + 0.5f) * abh;
    const float ycA = fminf(fmaxf(YA, 0.f), 39.f);
    const int   y0A = (int)ycA, y1iA = min(y0A + 1, 39);
    const float lyA = ycA - (float)y0A;
    const bool  vyA = (YA > -1.f) && (YA < 40.f);

    const float YB = by1 + (h + 0.5f) * bbh;
    const float ycB = fminf(fmaxf(YB, 0.f), 39.f);
    const int   y0B = (int)ycB, y1iB = min(y0B + 1, 39);
    const float lyB = ycB - (float)y0B;
    const bool  vyB = (YB > -1.f) && (YB < 40.f);

    // staging addresses
    const uint32_t wSw = ((uint32_t)(lane * 4)) ^ ((((uint32_t)lane >> 3) & 1u) << 2);
    uint32_t* wrA = s + wp * 132 + wSw;
    uint32_t* wrB = s + (wp + 8) * 132 + wSw;

    // read slots v0 = lane, v1 = lane + 32
    const int cc0 = lane >> 3,        ks0 = (lane >> 2) & 1, tg0 = lane & 3;
    const int cc1 = (lane + 32) >> 3, ks1 = ks0,             tg1 = tg0;
    const int tA0 = cc0 * 16 + ks0 * 8 + tg0;
    const int tA1 = cc1 * 16 + ks1 * 8 + tg1;
    const int pA0 = tA0 ^ (((tA0 >> 5) & 1) << 2);
    const int pA4 = (tA0 + 4) ^ (((tA0 >> 5) & 1) << 2);
    const int pB0 = tA1 ^ (((tA1 >> 5) & 1) << 2);
    const int pB4 = (tA1 + 4) ^ (((tA1 >> 5) & 1) << 2);

    for (int w = 0; w < 7; ++w) {
        // roi A weights
        const float XA = ax1 + (w + 0.5f) * abw;
        const float xcA = fminf(fmaxf(XA, 0.f), 39.f);
        const int   x0A = (int)xcA, x1iA = min(x0A + 1, 39);
        const float lxA = xcA - (float)x0A;
        float a00 = (1.f - lyA) * (1.f - lxA), a01 = (1.f - lyA) * lxA;
        float a10 = lyA * (1.f - lxA),         a11 = lyA * lxA;
        if (!(vyA && XA > -1.f && XA < 40.f)) { a00 = a01 = a10 = a11 = 0.f; }
        // roi B weights
        const float XB = bx1 + (w + 0.5f) * bbw;
        const float xcB = fminf(fmaxf(XB, 0.f), 39.f);
        const int   x0B = (int)xcB, x1iB = min(x0B + 1, 39);
        const float lxB = xcB - (float)x0B;
        float b00 = (1.f - lyB) * (1.f - lxB), b01 = (1.f - lyB) * lxB;
        float b10 = lyB * (1.f - lxB),         b11 = lyB * lxB;
        if (!(vyB && XB > -1.f && XB < 40.f)) { b00 = b01 = b10 = b11 = 0.f; }

        // coalesced corner loads (512B per corner per roi)
        U4 cA00, cA01, cA10, cA11, cB00, cB01, cB10, cB11;
        cA00.u = imgA[(y0A  * 40 + x0A ) * 32 + lane];
        cA01.u = imgA[(y0A  * 40 + x1iA) * 32 + lane];
        cA10.u = imgA[(y1iA * 40 + x0A ) * 32 + lane];
        cA11.u = imgA[(y1iA * 40 + x1iA) * 32 + lane];
        cB00.u = imgB[(y0B  * 40 + x0B ) * 32 + lane];
        cB01.u = imgB[(y0B  * 40 + x1iB) * 32 + lane];
        cB10.u = imgB[(y1iB * 40 + x0B ) * 32 + lane];
        cB11.u = imgB[(y1iB * 40 + x1iB) * 32 + lane];

        U4 oA, oB;
        #pragma unroll
        for (int j = 0; j < 4; ++j) {
            float2 f0 = __half22float2(cA00.h[j]);
            float2 f1 = __half22float2(cA01.h[j]);
            float2 f2 = __half22float2(cA10.h[j]);
            float2 f3 = __half22float2(cA11.h[j]);
            oA.h[j] = __floats2half2_rn(
                f0.x * a00 + f1.x * a01 + f2.x * a10 + f3.x * a11,
                f0.y * a00 + f1.y * a01 + f2.y * a10 + f3.y * a11);
            f0 = __half22float2(cB00.h[j]);
            f1 = __half22float2(cB01.h[j]);
            f2 = __half22float2(cB10.h[j]);
            f3 = __half22float2(cB11.h[j]);
            oB.h[j] = __floats2half2_rn(
                f0.x * b00 + f1.x * b01 + f2.x * b10 + f3.x * b11,
                f0.y * b00 + f1.y * b01 + f2.y * b10 + f3.y * b11);
        }
        *(uint4*)wrA = oA.u;
        *(uint4*)wrB = oB.u;
        __syncwarp();

        const int hw = h * 7 + w;
        {
            uint4 wv;
            wv.x = s[wp * 132 + pA0];
            wv.y = s[(wp + 8) * 132 + pA0];
            wv.z = s[wp * 132 + pA4];
            wv.w = s[(wp + 8) * 132 + pA4];
            *(uint4*)(outb + (size_t)(hw * 8 + cc0) * TILE_BYTES
                      + (ks0 * 32 + wp * 4 + tg0) * 16) = wv;
            wv.x = s[wp * 132 + pB0];
            wv.y = s[(wp + 8) * 132 + pB0];
            wv.z = s[wp * 132 + pB4];
            wv.w = s[(wp + 8) * 132 + pB4];
            *(uint4*)(outb + (size_t)(hw * 8 + cc1) * TILE_BYTES
                      + (ks1 * 32 + wp * 4 + tg1) * 16) = wv;
        }
        __syncwarp();
    }
}

// ================= generic fp16 MMA GEMM: 128x128x32, 4-stage cp.async =========
#define NSTAGE 4
#define STAGE_BYTES 16384
#define SM_TOTAL (NSTAGE * STAGE_BYTES)

__device__ __forceinline__ void cp16(void* smem_dst, const void* gmem_src) {
    unsigned s = (unsigned)__cvta_generic_to_shared(smem_dst);
    asm volatile("cp.async.cg.shared.global [%0], [%1], 16;" :: "r"(s), "l"(gmem_src));
}
__device__ __forceinline__ void cp_commit() { asm volatile("cp.async.commit_group;"); }
template<int N> __device__ __forceinline__ void cp_wait() {
    asm volatile("cp.async.wait_group %0;" :: "n"(N));
}

__global__ void __launch_bounds__(256, 1)
gemm_tc(const char* __restrict__ Afrag, const char* __restrict__ Bfrag, int nchunk,
        char* __restrict__ outFrag, float* __restrict__ outMax,
        const float* __restrict__ bias, const float* __restrict__ gamma,
        const float* __restrict__ beta, const float* __restrict__ mean,
        const float* __restrict__ var)
{
    extern __shared__ char sm[];
    const int tid = threadIdx.x, lane = tid & 31, wid = tid >> 5;
    const int warp_m = wid >> 1, warp_n = wid & 1;
    const int ntile = blockIdx.x, mtile = blockIdx.y;

    const char* Ag = Afrag + (size_t)mtile * nchunk * TILE_BYTES;
    const char* Bg = Bfrag + (size_t)ntile * nchunk * TILE_BYTES;

    float acc[2][8][4];
    #pragma unroll
    for (int mt = 0; mt < 2; ++mt)
        #pragma unroll
        for (int nt = 0; nt < 8; ++nt)
            #pragma unroll
            for (int j = 0; j < 4; ++j) acc[mt][nt][j] = 0.f;

    #pragma unroll
    for (int t = 0; t < 3; ++t) {
        char* sa = sm + t * STAGE_BYTES;
        #pragma unroll
        for (int i = 0; i < 2; ++i) {
            const int off = (tid + i * 256) * 16;
            cp16(sa + off,        Ag + (size_t)t * TILE_BYTES + off);
            cp16(sa + 8192 + off, Bg + (size_t)t * TILE_BYTES + off);
        }
        cp_commit();
    }

    const int aBase = (warp_m * 2) * 1024 + lane * 16;
    const int bBase = 8192 + (warp_n * 8) * 512 + lane * 8;

    for (int t = 0; t < nchunk; ++t) {
        cp_wait<2>();
        __syncthreads();

        if (t + 3 < nchunk) {
            char* sa = sm + ((t + 3) & 3) * STAGE_BYTES;
            #pragma unroll
            for (int i = 0; i < 2; ++i) {
                const int off = (tid + i * 256) * 16;
                cp16(sa + off,        Ag + (size_t)(t + 3) * TILE_BYTES + off);
                cp16(sa + 8192 + off, Bg + (size_t)(t + 3) * TILE_BYTES + off);
            }
        }
        cp_commit();

        const char* S = sm + (t & 3) * STAGE_BYTES;
        #pragma unroll
        for (int ks = 0; ks < 2; ++ks) {
            uint2 bf[8];
            #pragma unroll
            for (int nt = 0; nt < 8; ++nt)
                bf[nt] = *(const uint2*)(S + bBase + nt * 512 + ks * 256);
            uint4 af[2];
            #pragma unroll
            for (int mt = 0; mt < 2; ++mt)
                af[mt] = *(const uint4*)(S + aBase + mt * 1024 + ks * 512);
            #pragma unroll
            for (int nt = 0; nt < 8; ++nt) {
                #pragma unroll
                for (int mt = 0; mt < 2; ++mt) {
                    asm volatile(
                        "mma.sync.aligned.m16n8k16.row.col.f32.f16.f16.f32 "
                        "{%0,%1,%2,%3}, {%4,%5,%6,%7}, {%8,%9}, {%0,%1,%2,%3};"
                        : "+f"(acc[mt][nt][0]), "+f"(acc[mt][nt][1]),
                          "+f"(acc[mt][nt][2]), "+f"(acc[mt][nt][3])
                        : "r"(af[mt].x), "r"(af[mt].y), "r"(af[mt].z), "r"(af[mt].w),
                          "r"(bf[nt].x), "r"(bf[nt].y));
                }
            }
        }
    }

    const int g = lane >> 2, tg = lane & 3;

    if (outFrag) {
        __syncthreads();
        __half2* st2 = (__half2*)sm;
        #pragma unroll
        for (int nt = 0; nt < 8; ++nt) {
            const int c0l = warp_n * 64 + nt * 8 + tg * 2;
            const int cg0 = ntile * 128 + c0l;
            const float s0 = gamma[cg0]     * rsqrtf(var[cg0]     + EPS);
            const float s1 = gamma[cg0 + 1] * rsqrtf(var[cg0 + 1] + EPS);
            const float h0  = (bias[cg0]     - mean[cg0])     * s0 + beta[cg0];
            const float h1v = (bias[cg0 + 1] - mean[cg0 + 1]) * s1 + beta[cg0 + 1];
            #pragma unroll
            for (int mt = 0; mt < 2; ++mt) {
                const int rowl = warp_m * 32 + mt * 16 + g;
                st2[rowl * 66 + (c0l >> 1)] = __floats2half2_rn(
                    fmaxf(acc[mt][nt][0] * s0 + h0,  0.f),
                    fmaxf(acc[mt][nt][1] * s1 + h1v, 0.f));
                st2[(rowl + 8) * 66 + (c0l >> 1)] = __floats2half2_rn(
                    fmaxf(acc[mt][nt][2] * s0 + h0,  0.f),
                    fmaxf(acc[mt][nt][3] * s1 + h1v, 0.f));
            }
        }
        __syncthreads();
        char* dst = outFrag + (size_t)(mtile * 16 + ntile * 4) * TILE_BYTES;
        #pragma unroll
        for (int it = 0; it < 8; ++it) {
            const int u = tid + it * 256;        // 0..2047 (16B slots)
            const int chunkl = u >> 9, sidx = u & 511;
            const int subr = sidx >> 6, rem = sidx & 63;
            const int ks2 = rem >> 5, ln = rem & 31;
            const int g2 = ln >> 2, tg2 = ln & 3;
            const int row = subr * 16 + g2;
            const int kp = chunkl * 16 + ks2 * 8 + tg2;
            uint4 wv;
            wv.x = *(const uint32_t*)&st2[row * 66 + kp];
            wv.y = *(const uint32_t*)&st2[(row + 8) * 66 + kp];
            wv.z = *(const uint32_t*)&st2[row * 66 + kp + 4];
            wv.w = *(const uint32_t*)&st2[(row + 8) * 66 + kp + 4];
            *(uint4*)(dst + (size_t)chunkl * TILE_BYTES + subr * 1024 + rem * 16) = wv;
        }
    } else {
        const int n0 = ntile * 128 + warp_n * 64;
        #pragma unroll
        for (int nt = 0; nt < 8; ++nt) {
            const int c0 = n0 + nt * 8 + tg * 2;
            const float s0 = gamma[c0]     * rsqrtf(var[c0]     + EPS);
            const float s1 = gamma[c0 + 1] * rsqrtf(var[c0 + 1] + EPS);
            const float h0  = (bias[c0]     - mean[c0])     * s0 + beta[c0];
            const float h1v = (bias[c0 + 1] - mean[c0 + 1]) * s1 + beta[c0 + 1];
            #pragma unroll
            for (int mt = 0; mt < 2; ++mt) {
                float v0 = fmaxf(acc[mt][nt][0] * s0 + h0,  0.f);
                float v1 = fmaxf(acc[mt][nt][1] * s1 + h1v, 0.f);
                float v2 = fmaxf(acc[mt][nt][2] * s0 + h0,  0.f);
                float v3 = fmaxf(acc[mt][nt][3] * s1 + h1v, 0.f);
                #pragma unroll
                for (int d = 4; d <= 16; d <<= 1) {
                    v0 = fmaxf(v0, __shfl_xor_sync(0xffffffffu, v0, d));
                    v1 = fmaxf(v1, __shfl_xor_sync(0xffffffffu, v1, d));
                    v2 = fmaxf(v2, __shfl_xor_sync(0xffffffffu, v2, d));
                    v3 = fmaxf(v3, __shfl_xor_sync(0xffffffffu, v3, d));
                }
                if (lane < 4) {
                    const int node0 = mtile * 16 + warp_m * 4 + mt * 2;
                    float2 a; a.x = v0; a.y = v1;
                    float2 b; b.x = v2; b.y = v3;
                    *(float2*)&outMax[(size_t)node0 * DD + c0] = a;
                    *(float2*)&outMax[(size_t)(node0 + 1) * DD + c0] = b;
                }
            }
        }
    }
}

// ---------------- launch ----------------
extern "C" void kernel_launch(void* const* d_in, const int* in_sizes, int n_in,
                              void* d_out, int out_size)
{
    const float* images = (const float*)d_in[0];
    const int*   kf     = (const int*)  d_in[1];
    const float* boxes  = (const float*)d_in[2];
    const float* w1     = (const float*)d_in[3];
    const float* b1     = (const float*)d_in[4];
    const float* g1     = (const float*)d_in[5];
    const float* bt1    = (const float*)d_in[6];
    const float* m1     = (const float*)d_in[7];
    const float* v1     = (const float*)d_in[8];
    const float* w2     = (const float*)d_in[9];
    const float* b2     = (const float*)d_in[10];
    const float* g2     = (const float*)d_in[11];
    const float* bt2    = (const float*)d_in[12];
    const float* m2     = (const float*)d_in[13];
    const float* v2     = (const float*)d_in[14];
    float* out = (float*)d_out;

    char *roiT, *w1tT, *h1T, *w2T;
    cudaGetSymbolAddress((void**)&roiT, g_roiT);
    cudaGetSymbolAddress((void**)&w1tT, g_w1tT);
    cudaGetSymbolAddress((void**)&h1T,  g_h1T);
    cudaGetSymbolAddress((void**)&w2T,  g_w2T);

    cudaFuncSetAttribute(gemm_tc, cudaFuncAttributeMaxDynamicSharedMemorySize, SM_TOTAL);

    transpose_img<<<dim3(NPIX / 32, CCH / 64, NF), dim3(32, 8)>>>(images);
    transpose_w1<<<HID, 256>>>(w1);
    repack_w2<<<DD, 128>>>(w2);
    roi_gather_frag<<<dim3(256, 7), 256>>>(kf, boxes);
    gemm_tc<<<dim3(4, 32), 256, SM_TOTAL>>>(
        roiT, w1tT, NCHUNK, h1T, nullptr, b1, g1, bt1, m1, v1);
    gemm_tc<<<dim3(4, 32), 256, SM_TOTAL>>>(
        h1T, w2T, 16, nullptr, out, b2, g2, bt2, m2, v2);
}

// round 8
// speedup vs baseline: 5.7205x; 1.0137x over previous
#include <cuda_runtime.h>
#include <cuda_fp16.h>
#include <cstdint>

#define EPS 0.001f
#define NF   64
#define CCH  256
#define NPIX 1600        // 40*40
#define RTOT 4096        // N*K = 512*8
#define HID  512
#define DD   512
#define K1   12544       // 49*256
#define NCHUNK 392       // K1/32
#define TILE_BYTES 8192  // 128 rows x 32 k (fp16), fragment order
#define TILE_HALVES 4096

// ---- scratch (static __device__ per allocation rules) ----
__device__ __half g_imgH[(size_t)NF * NPIX * CCH];            // NHWC fp16 images (52 MB)
__device__ __half g_w1tT[(size_t)4 * NCHUNK * TILE_HALVES];   // B1 frag tiles (paired-nsub layout)
__device__ __half g_roiT[(size_t)32 * NCHUNK * TILE_HALVES];  // A1 frag tiles (103 MB)
__device__ __half g_h1T [(size_t)32 * 16 * TILE_HALVES];      // h1 as A2 frag tiles
__device__ __half g_w2T [(size_t)4 * 16 * TILE_HALVES];       // B2 frag tiles (paired-nsub layout)

// ---------------- image transpose NCHW f32 -> NHWC f16 ----------------
__global__ void transpose_img(const float* __restrict__ in)
{
    __shared__ float s[64][33];
    const int f  = blockIdx.z;
    const float* src = in + (size_t)f * CCH * NPIX;
    const int p0 = blockIdx.x * 32;
    const int c0 = blockIdx.y * 64;
    #pragma unroll
    for (int i = threadIdx.y; i < 64; i += 8)
        s[i][threadIdx.x] = src[(size_t)(c0 + i) * NPIX + p0 + threadIdx.x];
    __syncthreads();
    __half2* dst = (__half2*)g_imgH + (size_t)f * NPIX * 128 + (c0 >> 1) + threadIdx.x;
    #pragma unroll
    for (int i = threadIdx.y; i < 32; i += 8)
        dst[(size_t)(p0 + i) * 128] =
            __floats2half2_rn(s[2 * threadIdx.x][i], s[2 * threadIdx.x + 1][i]);
}

// ---------------- w1 -> fp16 B-fragment tiles (paired-nsub 16B slots) ----------------
// B[n=o][k], k = hw*256 + c; source w1[o][c*49+hw], smem-staged for coalesced reads.
// slot(np, ks, lane) 16B = {b0,b1}[nsub=2np] ++ {b0,b1}[nsub=2np+1]
__global__ void __launch_bounds__(128) transpose_w1(const float* __restrict__ w1)
{
    __shared__ __half s[K1];
    const int o = blockIdx.x;
    const int ntile = o >> 7, col = o & 127;
    const int nsub = col >> 3, np = nsub >> 1, hf = nsub & 1, gcol = col & 7;
    const float* src = w1 + (size_t)o * K1;
    for (int i = threadIdx.x; i < K1; i += 128)
        s[i] = __float2half(src[i]);
    __syncthreads();
    char* base = (char*)g_w1tT + (size_t)ntile * NCHUNK * TILE_BYTES;
    for (int k2 = threadIdx.x; k2 < K1 / 2; k2 += 128) {
        const int k = k2 * 2;
        const int hw = k >> 8, c = k & 255;
        const __half2 v = __halves2half2(s[c * 49 + hw], s[(c + 1) * 49 + hw]);
        const int chunk = k >> 5, kk = k & 31;
        const int ks = kk >> 4, kkk = kk & 15;
        const int tg = (kkk & 7) >> 1;
        const int b_idx = (kkk >= 8) ? 1 : 0;
        const uint32_t off = np * 1024 + ks * 512 + (gcol * 4 + tg) * 16 + hf * 8 + b_idx * 4;
        *(__half2*)(base + (size_t)chunk * TILE_BYTES + off) = v;
    }
}

// ---------------- w2 -> fp16 B-fragment tiles (paired-nsub) ----------------
__global__ void repack_w2(const float* __restrict__ w2)
{
    const int o = blockIdx.x;
    const int ntile = o >> 7, col = o & 127;
    const int nsub = col >> 3, np = nsub >> 1, hf = nsub & 1, gcol = col & 7;
    for (int k2 = threadIdx.x; k2 < DD / 2; k2 += blockDim.x) {
        const int k = k2 * 2;
        const float v0 = __ldg(&w2[(size_t)o * DD + k]);
        const float v1 = __ldg(&w2[(size_t)o * DD + k + 1]);
        const int chunk = k >> 5, kk = k & 31;
        const int ks = kk >> 4, kkk = kk & 15;
        const int tg = (kkk & 7) >> 1;
        const int b_idx = (kkk >= 8) ? 1 : 0;
        const uint32_t off = np * 1024 + ks * 512 + (gcol * 4 + tg) * 16 + hf * 8 + b_idx * 4;
        *(__half2*)((char*)g_w2T + (size_t)(ntile * 16 + chunk) * TILE_BYTES + off) =
            __floats2half2_rn(v0, v1);
    }
}

// ---------------- fused RoIAlign gather -> fp16 A fragment tiles ----------------
// (unchanged from R7 — proven at 44.7us)
union U4 { uint4 u; __half2 h[4]; };

__global__ void __launch_bounds__(256) roi_gather_frag(const int* __restrict__ kf,
                                                       const float* __restrict__ boxes)
{
    __shared__ uint32_t s[16 * 132];
    const int blk = blockIdx.x;
    const int h   = blockIdx.y;
    const int mtile = blk >> 3, sub = blk & 7;
    const int tid = threadIdx.x, lane = tid & 31, wp = tid >> 5;
    const int rA = blk * 16 + wp, rB = rA + 8;

    const int fA = kf[rA], fB = kf[rB];
    const float ax1 = boxes[rA * 4 + 0] * 40.f, ay1 = boxes[rA * 4 + 1] * 40.f;
    const float ax2 = boxes[rA * 4 + 2] * 40.f, ay2 = boxes[rA * 4 + 3] * 40.f;
    const float bx1 = boxes[rB * 4 + 0] * 40.f, by1 = boxes[rB * 4 + 1] * 40.f;
    const float bx2 = boxes[rB * 4 + 2] * 40.f, by2 = boxes[rB * 4 + 3] * 40.f;
    const float abw = (ax2 - ax1) * (1.f / 7.f), abh = (ay2 - ay1) * (1.f / 7.f);
    const float bbw = (bx2 - bx1) * (1.f / 7.f), bbh = (by2 - by1) * (1.f / 7.f);

    const uint4* imgA = (const uint4*)(g_imgH + (size_t)fA * NPIX * CCH);
    const uint4* imgB = (const uint4*)(g_imgH + (size_t)fB * NPIX * CCH);
    char* outb = (char*)g_roiT + (size_t)mtile * NCHUNK * TILE_BYTES + sub * 1024;

    const float YA = ay1 + (h + 0.5f) * abh;
    const float ycA = fminf(fmaxf(YA, 0.f), 39.f);
    const int   y0A = (int)ycA, y1iA = min(y0A + 1, 39);
    const float lyA = ycA - (float)y0A;
    const bool  vyA = (YA > -1.f) && (YA < 40.f);

    const float YB = by1 + (h + 0.5f) * bbh;
    const float ycB = fminf(fmaxf(YB, 0.f), 39.f);
    const int   y0B = (int)ycB, y1iB = min(y0B + 1, 39);
    const float lyB = ycB - (float)y0B;
    const bool  vyB = (YB > -1.f) && (YB < 40.f);

    const uint32_t wSw = ((uint32_t)(lane * 4)) ^ ((((uint32_t)lane >> 3) & 1u) << 2);
    uint32_t* wrA = s + wp * 132 + wSw;
    uint32_t* wrB = s + (wp + 8) * 132 + wSw;

    const int cc0 = lane >> 3,        ks0 = (lane >> 2) & 1, tg0 = lane & 3;
    const int cc1 = (lane + 32) >> 3, ks1 = ks0,             tg1 = tg0;
    const int tA0 = cc0 * 16 + ks0 * 8 + tg0;
    const int tA1 = cc1 * 16 + ks1 * 8 + tg1;
    const int pA0 = tA0 ^ (((tA0 >> 5) & 1) << 2);
    const int pA4 = (tA0 + 4) ^ (((tA0 >> 5) & 1) << 2);
    const int pB0 = tA1 ^ (((tA1 >> 5) & 1) << 2);
    const int pB4 = (tA1 + 4) ^ (((tA1 >> 5) & 1) << 2);

    for (int w = 0; w < 7; ++w) {
        const float XA = ax1 + (w + 0.5f) * abw;
        const float xcA = fminf(fmaxf(XA, 0.f), 39.f);
        const int   x0A = (int)xcA, x1iA = min(x0A + 1, 39);
        const float lxA = xcA - (float)x0A;
        float a00 = (1.f - lyA) * (1.f - lxA), a01 = (1.f - lyA) * lxA;
        float a10 = lyA * (1.f - lxA),         a11 = lyA * lxA;
        if (!(vyA && XA > -1.f && XA < 40.f)) { a00 = a01 = a10 = a11 = 0.f; }
        const float XB = bx1 + (w + 0.5f) * bbw;
        const float xcB = fminf(fmaxf(XB, 0.f), 39.f);
        const int   x0B = (int)xcB, x1iB = min(x0B + 1, 39);
        const float lxB = xcB - (float)x0B;
        float b00 = (1.f - lyB) * (1.f - lxB), b01 = (1.f - lyB) * lxB;
        float b10 = lyB * (1.f - lxB),         b11 = lyB * lxB;
        if (!(vyB && XB > -1.f && XB < 40.f)) { b00 = b01 = b10 = b11 = 0.f; }

        U4 cA00, cA01, cA10, cA11, cB00, cB01, cB10, cB11;
        cA00.u = imgA[(y0A  * 40 + x0A ) * 32 + lane];
        cA01.u = imgA[(y0A  * 40 + x1iA) * 32 + lane];
        cA10.u = imgA[(y1iA * 40 + x0A ) * 32 + lane];
        cA11.u = imgA[(y1iA * 40 + x1iA) * 32 + lane];
        cB00.u = imgB[(y0B  * 40 + x0B ) * 32 + lane];
        cB01.u = imgB[(y0B  * 40 + x1iB) * 32 + lane];
        cB10.u = imgB[(y1iB * 40 + x0B ) * 32 + lane];
        cB11.u = imgB[(y1iB * 40 + x1iB) * 32 + lane];

        U4 oA, oB;
        #pragma unroll
        for (int j = 0; j < 4; ++j) {
            float2 f0 = __half22float2(cA00.h[j]);
            float2 f1 = __half22float2(cA01.h[j]);
            float2 f2 = __half22float2(cA10.h[j]);
            float2 f3 = __half22float2(cA11.h[j]);
            oA.h[j] = __floats2half2_rn(
                f0.x * a00 + f1.x * a01 + f2.x * a10 + f3.x * a11,
                f0.y * a00 + f1.y * a01 + f2.y * a10 + f3.y * a11);
            f0 = __half22float2(cB00.h[j]);
            f1 = __half22float2(cB01.h[j]);
            f2 = __half22float2(cB10.h[j]);
            f3 = __half22float2(cB11.h[j]);
            oB.h[j] = __floats2half2_rn(
                f0.x * b00 + f1.x * b01 + f2.x * b10 + f3.x * b11,
                f0.y * b00 + f1.y * b01 + f2.y * b10 + f3.y * b11);
        }
        *(uint4*)wrA = oA.u;
        *(uint4*)wrB = oB.u;
        __syncwarp();

        const int hw = h * 7 + w;
        {
            uint4 wv;
            wv.x = s[wp * 132 + pA0];
            wv.y = s[(wp + 8) * 132 + pA0];
            wv.z = s[wp * 132 + pA4];
            wv.w = s[(wp + 8) * 132 + pA4];
            *(uint4*)(outb + (size_t)(hw * 8 + cc0) * TILE_BYTES
                      + (ks0 * 32 + wp * 4 + tg0) * 16) = wv;
            wv.x = s[wp * 132 + pB0];
            wv.y = s[(wp + 8) * 132 + pB0];
            wv.z = s[wp * 132 + pB4];
            wv.w = s[(wp + 8) * 132 + pB4];
            *(uint4*)(outb + (size_t)(hw * 8 + cc1) * TILE_BYTES
                      + (ks1 * 32 + wp * 4 + tg1) * 16) = wv;
        }
        __syncwarp();
    }
}

// ========== fp16 MMA GEMM: 128x128x32 CTA, 4 warps, 64x64 warp tile ==========
#define NSTAGE 4
#define STAGE_BYTES 16384
#define SM_TOTAL (NSTAGE * STAGE_BYTES)

__device__ __forceinline__ void cp16(void* smem_dst, const void* gmem_src) {
    unsigned s = (unsigned)__cvta_generic_to_shared(smem_dst);
    asm volatile("cp.async.cg.shared.global [%0], [%1], 16;" :: "r"(s), "l"(gmem_src));
}
__device__ __forceinline__ void cp_commit() { asm volatile("cp.async.commit_group;"); }
template<int N> __device__ __forceinline__ void cp_wait() {
    asm volatile("cp.async.wait_group %0;" :: "n"(N));
}

__global__ void __launch_bounds__(128, 1)
gemm_tc(const char* __restrict__ Afrag, const char* __restrict__ Bfrag, int nchunk,
        char* __restrict__ outFrag, float* __restrict__ outMax,
        const float* __restrict__ bias, const float* __restrict__ gamma,
        const float* __restrict__ beta, const float* __restrict__ mean,
        const float* __restrict__ var)
{
    extern __shared__ char sm[];
    const int tid = threadIdx.x, lane = tid & 31, wid = tid >> 5;
    const int warp_m = wid >> 1, warp_n = wid & 1;
    const int ntile = blockIdx.x, mtile = blockIdx.y;

    const char* Ag = Afrag + (size_t)mtile * nchunk * TILE_BYTES;
    const char* Bg = Bfrag + (size_t)ntile * nchunk * TILE_BYTES;

    float acc[4][8][4];
    #pragma unroll
    for (int mt = 0; mt < 4; ++mt)
        #pragma unroll
        for (int nt = 0; nt < 8; ++nt)
            #pragma unroll
            for (int j = 0; j < 4; ++j) acc[mt][nt][j] = 0.f;

    #pragma unroll
    for (int t = 0; t < 3; ++t) {
        char* sa = sm + t * STAGE_BYTES;
        #pragma unroll
        for (int i = 0; i < 4; ++i) {
            const int off = (tid + i * 128) * 16;
            cp16(sa + off,        Ag + (size_t)t * TILE_BYTES + off);
            cp16(sa + 8192 + off, Bg + (size_t)t * TILE_BYTES + off);
        }
        cp_commit();
    }

    const int aBase = warp_m * 4096 + lane * 16;
    const int bBase = 8192 + warp_n * 4096 + lane * 16;

    for (int t = 0; t < nchunk; ++t) {
        cp_wait<2>();
        __syncthreads();

        if (t + 3 < nchunk) {
            char* sa = sm + ((t + 3) & 3) * STAGE_BYTES;
            #pragma unroll
            for (int i = 0; i < 4; ++i) {
                const int off = (tid + i * 128) * 16;
                cp16(sa + off,        Ag + (size_t)(t + 3) * TILE_BYTES + off);
                cp16(sa + 8192 + off, Bg + (size_t)(t + 3) * TILE_BYTES + off);
            }
        }
        cp_commit();

        const char* S = sm + (t & 3) * STAGE_BYTES;
        #pragma unroll
        for (int ks = 0; ks < 2; ++ks) {
            uint4 af[4];
            #pragma unroll
            for (int mt = 0; mt < 4; ++mt)
                af[mt] = *(const uint4*)(S + aBase + mt * 1024 + ks * 512);
            uint4 bq[4];
            #pragma unroll
            for (int np = 0; np < 4; ++np)
                bq[np] = *(const uint4*)(S + bBase + np * 1024 + ks * 512);
            #pragma unroll
            for (int np = 0; np < 4; ++np) {
                #pragma unroll
                for (int mt = 0; mt < 4; ++mt) {
                    asm volatile(
                        "mma.sync.aligned.m16n8k16.row.col.f32.f16.f16.f32 "
                        "{%0,%1,%2,%3}, {%4,%5,%6,%7}, {%8,%9}, {%0,%1,%2,%3};"
                        : "+f"(acc[mt][np * 2][0]), "+f"(acc[mt][np * 2][1]),
                          "+f"(acc[mt][np * 2][2]), "+f"(acc[mt][np * 2][3])
                        : "r"(af[mt].x), "r"(af[mt].y), "r"(af[mt].z), "r"(af[mt].w),
                          "r"(bq[np].x), "r"(bq[np].y));
                    asm volatile(
                        "mma.sync.aligned.m16n8k16.row.col.f32.f16.f16.f32 "
                        "{%0,%1,%2,%3}, {%4,%5,%6,%7}, {%8,%9}, {%0,%1,%2,%3};"
                        : "+f"(acc[mt][np * 2 + 1][0]), "+f"(acc[mt][np * 2 + 1][1]),
                          "+f"(acc[mt][np * 2 + 1][2]), "+f"(acc[mt][np * 2 + 1][3])
                        : "r"(af[mt].x), "r"(af[mt].y), "r"(af[mt].z), "r"(af[mt].w),
                          "r"(bq[np].z), "r"(bq[np].w));
                }
            }
        }
    }

    const int g = lane >> 2, tg = lane & 3;

    if (outFrag) {
        // stage BN+ReLU tile in smem as half2 (stride 66), then emit A-frag fp16 tiles
        __syncthreads();
        __half2* st2 = (__half2*)sm;
        #pragma unroll
        for (int nt = 0; nt < 8; ++nt) {
            const int c0l = warp_n * 64 + nt * 8 + tg * 2;
            const int cg0 = ntile * 128 + c0l;
            const float s0 = gamma[cg0]     * rsqrtf(var[cg0]     + EPS);
            const float s1 = gamma[cg0 + 1] * rsqrtf(var[cg0 + 1] + EPS);
            const float h0  = (bias[cg0]     - mean[cg0])     * s0 + beta[cg0];
            const float h1v = (bias[cg0 + 1] - mean[cg0 + 1]) * s1 + beta[cg0 + 1];
            #pragma unroll
            for (int mt = 0; mt < 4; ++mt) {
                const int rowl = warp_m * 64 + mt * 16 + g;
                st2[rowl * 66 + (c0l >> 1)] = __floats2half2_rn(
                    fmaxf(acc[mt][nt][0] * s0 + h0,  0.f),
                    fmaxf(acc[mt][nt][1] * s1 + h1v, 0.f));
                st2[(rowl + 8) * 66 + (c0l >> 1)] = __floats2half2_rn(
                    fmaxf(acc[mt][nt][2] * s0 + h0,  0.f),
                    fmaxf(acc[mt][nt][3] * s1 + h1v, 0.f));
            }
        }
        __syncthreads();
        char* dst = outFrag + (size_t)(mtile * 16 + ntile * 4) * TILE_BYTES;
        #pragma unroll
        for (int it = 0; it < 16; ++it) {
            const int u = tid + it * 128;        // 0..2047 (16B slots)
            const int chunkl = u >> 9, sidx = u & 511;
            const int subr = sidx >> 6, rem = sidx & 63;
            const int ks2 = rem >> 5, ln = rem & 31;
            const int g2 = ln >> 2, tg2 = ln & 3;
            const int row = subr * 16 + g2;
            const int kp = chunkl * 16 + ks2 * 8 + tg2;
            uint4 wv;
            wv.x = *(const uint32_t*)&st2[row * 66 + kp];
            wv.y = *(const uint32_t*)&st2[(row + 8) * 66 + kp];
            wv.z = *(const uint32_t*)&st2[row * 66 + kp + 4];
            wv.w = *(const uint32_t*)&st2[(row + 8) * 66 + kp + 4];
            *(uint4*)(dst + (size_t)chunkl * TILE_BYTES + subr * 1024 + rem * 16) = wv;
        }
    } else {
        // fused BN + ReLU + max over 8-row groups -> outMax[node][col]
        const int n0 = ntile * 128 + warp_n * 64;
        #pragma unroll
        for (int nt = 0; nt < 8; ++nt) {
            const int c0 = n0 + nt * 8 + tg * 2;
            const float s0 = gamma[c0]     * rsqrtf(var[c0]     + EPS);
            const float s1 = gamma[c0 + 1] * rsqrtf(var[c0 + 1] + EPS);
            const float h0  = (bias[c0]     - mean[c0])     * s0 + beta[c0];
            const float h1v = (bias[c0 + 1] - mean[c0 + 1]) * s1 + beta[c0 + 1];
            #pragma unroll
            for (int mt = 0; mt < 4; ++mt) {
                float v0 = fmaxf(acc[mt][nt][0] * s0 + h0,  0.f);
                float v1 = fmaxf(acc[mt][nt][1] * s1 + h1v, 0.f);
                float v2 = fmaxf(acc[mt][nt][2] * s0 + h0,  0.f);
                float v3 = fmaxf(acc[mt][nt][3] * s1 + h1v, 0.f);
                #pragma unroll
                for (int d = 4; d <= 16; d <<= 1) {
                    v0 = fmaxf(v0, __shfl_xor_sync(0xffffffffu, v0, d));
                    v1 = fmaxf(v1, __shfl_xor_sync(0xffffffffu, v1, d));
                    v2 = fmaxf(v2, __shfl_xor_sync(0xffffffffu, v2, d));
                    v3 = fmaxf(v3, __shfl_xor_sync(0xffffffffu, v3, d));
                }
                if (lane < 4) {
                    const int node0 = mtile * 16 + warp_m * 8 + mt * 2;
                    float2 a; a.x = v0; a.y = v1;
                    float2 b; b.x = v2; b.y = v3;
                    *(float2*)&outMax[(size_t)node0 * DD + c0] = a;
                    *(float2*)&outMax[(size_t)(node0 + 1) * DD + c0] = b;
                }
            }
        }
    }
}

// ---------------- launch ----------------
extern "C" void kernel_launch(void* const* d_in, const int* in_sizes, int n_in,
                              void* d_out, int out_size)
{
    const float* images = (const float*)d_in[0];
    const int*   kf     = (const int*)  d_in[1];
    const float* boxes  = (const float*)d_in[2];
    const float* w1     = (const float*)d_in[3];
    const float* b1     = (const float*)d_in[4];
    const float* g1     = (const float*)d_in[5];
    const float* bt1    = (const float*)d_in[6];
    const float* m1     = (const float*)d_in[7];
    const float* v1     = (const float*)d_in[8];
    const float* w2     = (const float*)d_in[9];
    const float* b2     = (const float*)d_in[10];
    const float* g2     = (const float*)d_in[11];
    const float* bt2    = (const float*)d_in[12];
    const float* m2     = (const float*)d_in[13];
    const float* v2     = (const float*)d_in[14];
    float* out = (float*)d_out;

    char *roiT, *w1tT, *h1T, *w2T;
    cudaGetSymbolAddress((void**)&roiT, g_roiT);
    cudaGetSymbolAddress((void**)&w1tT, g_w1tT);
    cudaGetSymbolAddress((void**)&h1T,  g_h1T);
    cudaGetSymbolAddress((void**)&w2T,  g_w2T);

    cudaFuncSetAttribute(gemm_tc, cudaFuncAttributeMaxDynamicSharedMemorySize, SM_TOTAL);

    transpose_img<<<dim3(NPIX / 32, CCH / 64, NF), dim3(32, 8)>>>(images);
    transpose_w1<<<HID, 128>>>(w1);
    repack_w2<<<DD, 128>>>(w2);
    roi_gather_frag<<<dim3(256, 7), 256>>>(kf, boxes);
    gemm_tc<<<dim3(4, 32), 128, SM_TOTAL>>>(
        roiT, w1tT, NCHUNK, h1T, nullptr, b1, g1, bt1, m1, v1);
    gemm_tc<<<dim3(4, 32), 128, SM_TOTAL>>>(
        h1T, w2T, 16, nullptr, out, b2, g2, bt2, m2, v2);
}

// round 10
// speedup vs baseline: 6.2889x; 1.0994x over previous
#include <cuda_runtime.h>
#include <cuda_fp16.h>
#include <cstdint>

#define EPS 0.001f
#define NF   64
#define CCH  256
#define NPIX 1600        // 40*40
#define RTOT 4096        // N*K = 512*8
#define HID  512
#define DD   512
#define K1   12544       // 49*256
#define NCHUNK 392       // K1/32
#define TILE_BYTES 8192  // 128 rows x 32 k (fp16), fragment order
#define TILE_HALVES 4096

// ---- scratch (static __device__ per allocation rules) ----
__device__ __half g_imgH[(size_t)NF * NPIX * CCH];            // NHWC fp16 images (52 MB)
__device__ __half g_w1tT[(size_t)4 * NCHUNK * TILE_HALVES];   // B1 frag tiles (paired-nsub layout)
__device__ __half g_roiT[(size_t)32 * NCHUNK * TILE_HALVES];  // A1 frag tiles (103 MB)
__device__ __half g_h1T [(size_t)32 * 16 * TILE_HALVES];      // h1 as A2 frag tiles
__device__ __half g_w2T [(size_t)4 * 16 * TILE_HALVES];       // B2 frag tiles (paired-nsub layout)

// ---------------- image transpose NCHW f32 -> NHWC f16 ----------------
__global__ void transpose_img(const float* __restrict__ in)
{
    __shared__ float s[64][33];
    const int f  = blockIdx.z;
    const float* src = in + (size_t)f * CCH * NPIX;
    const int p0 = blockIdx.x * 32;
    const int c0 = blockIdx.y * 64;
    #pragma unroll
    for (int i = threadIdx.y; i < 64; i += 8)
        s[i][threadIdx.x] = src[(size_t)(c0 + i) * NPIX + p0 + threadIdx.x];
    __syncthreads();
    __half2* dst = (__half2*)g_imgH + (size_t)f * NPIX * 128 + (c0 >> 1) + threadIdx.x;
    #pragma unroll
    for (int i = threadIdx.y; i < 32; i += 8)
        dst[(size_t)(p0 + i) * 128] =
            __floats2half2_rn(s[2 * threadIdx.x][i], s[2 * threadIdx.x + 1][i]);
}

// ---------------- w1 -> fp16 B-fragment tiles (paired-nsub 16B slots) ----------------
__global__ void __launch_bounds__(128) transpose_w1(const float* __restrict__ w1)
{
    __shared__ __half s[K1];
    const int o = blockIdx.x;
    const int ntile = o >> 7, col = o & 127;
    const int nsub = col >> 3, np = nsub >> 1, hf = nsub & 1, gcol = col & 7;
    const float* src = w1 + (size_t)o * K1;
    for (int i = threadIdx.x; i < K1; i += 128)
        s[i] = __float2half(src[i]);
    __syncthreads();
    char* base = (char*)g_w1tT + (size_t)ntile * NCHUNK * TILE_BYTES;
    for (int k2 = threadIdx.x; k2 < K1 / 2; k2 += 128) {
        const int k = k2 * 2;
        const int hw = k >> 8, c = k & 255;
        const __half2 v = __halves2half2(s[c * 49 + hw], s[(c + 1) * 49 + hw]);
        const int chunk = k >> 5, kk = k & 31;
        const int ks = kk >> 4, kkk = kk & 15;
        const int tg = (kkk & 7) >> 1;
        const int b_idx = (kkk >= 8) ? 1 : 0;
        const uint32_t off = np * 1024 + ks * 512 + (gcol * 4 + tg) * 16 + hf * 8 + b_idx * 4;
        *(__half2*)(base + (size_t)chunk * TILE_BYTES + off) = v;
    }
}

// ---------------- w2 -> fp16 B-fragment tiles (paired-nsub) ----------------
__global__ void repack_w2(const float* __restrict__ w2)
{
    const int o = blockIdx.x;
    const int ntile = o >> 7, col = o & 127;
    const int nsub = col >> 3, np = nsub >> 1, hf = nsub & 1, gcol = col & 7;
    for (int k2 = threadIdx.x; k2 < DD / 2; k2 += blockDim.x) {
        const int k = k2 * 2;
        const float v0 = __ldg(&w2[(size_t)o * DD + k]);
        const float v1 = __ldg(&w2[(size_t)o * DD + k + 1]);
        const int chunk = k >> 5, kk = k & 31;
        const int ks = kk >> 4, kkk = kk & 15;
        const int tg = (kkk & 7) >> 1;
        const int b_idx = (kkk >= 8) ? 1 : 0;
        const uint32_t off = np * 1024 + ks * 512 + (gcol * 4 + tg) * 16 + hf * 8 + b_idx * 4;
        *(__half2*)((char*)g_w2T + (size_t)(ntile * 16 + chunk) * TILE_BYTES + off) =
            __floats2half2_rn(v0, v1);
    }
}

// ---------------- fused RoIAlign gather -> fp16 A fragment tiles ----------------
// (unchanged from R7/R8 — proven at ~45us)
union U4 { uint4 u; __half2 h[4]; };

__global__ void __launch_bounds__(256) roi_gather_frag(const int* __restrict__ kf,
                                                       const float* __restrict__ boxes)
{
    __shared__ uint32_t s[16 * 132];
    const int blk = blockIdx.x;
    const int h   = blockIdx.y;
    const int mtile = blk >> 3, sub = blk & 7;
    const int tid = threadIdx.x, lane = tid & 31, wp = tid >> 5;
    const int rA = blk * 16 + wp, rB = rA + 8;

    const int fA = kf[rA], fB = kf[rB];
    const float ax1 = boxes[rA * 4 + 0] * 40.f, ay1 = boxes[rA * 4 + 1] * 40.f;
    const float ax2 = boxes[rA * 4 + 2] * 40.f, ay2 = boxes[rA * 4 + 3] * 40.f;
    const float bx1 = boxes[rB * 4 + 0] * 40.f, by1 = boxes[rB * 4 + 1] * 40.f;
    const float bx2 = boxes[rB * 4 + 2] * 40.f, by2 = boxes[rB * 4 + 3] * 40.f;
    const float abw = (ax2 - ax1) * (1.f / 7.f), abh = (ay2 - ay1) * (1.f / 7.f);
    const float bbw = (bx2 - bx1) * (1.f / 7.f), bbh = (by2 - by1) * (1.f / 7.f);

    const uint4* imgA = (const uint4*)(g_imgH + (size_t)fA * NPIX * CCH);
    const uint4* imgB = (const uint4*)(g_imgH + (size_t)fB * NPIX * CCH);
    char* outb = (char*)g_roiT + (size_t)mtile * NCHUNK * TILE_BYTES + sub * 1024;

    const float YA = ay1 + (h + 0.5f) * abh;
    const float ycA = fminf(fmaxf(YA, 0.f), 39.f);
    const int   y0A = (int)ycA, y1iA = min(y0A + 1, 39);
    const float lyA = ycA - (float)y0A;
    const bool  vyA = (YA > -1.f) && (YA < 40.f);

    const float YB = by1 + (h + 0.5f) * bbh;
    const float ycB = fminf(fmaxf(YB, 0.f), 39.f);
    const int   y0B = (int)ycB, y1iB = min(y0B + 1, 39);
    const float lyB = ycB - (float)y0B;
    const bool  vyB = (YB > -1.f) && (YB < 40.f);

    const uint32_t wSw = ((uint32_t)(lane * 4)) ^ ((((uint32_t)lane >> 3) & 1u) << 2);
    uint32_t* wrA = s + wp * 132 + wSw;
    uint32_t* wrB = s + (wp + 8) * 132 + wSw;

    const int cc0 = lane >> 3,        ks0 = (lane >> 2) & 1, tg0 = lane & 3;
    const int cc1 = (lane + 32) >> 3, ks1 = ks0,             tg1 = tg0;
    const int tA0 = cc0 * 16 + ks0 * 8 + tg0;
    const int tA1 = cc1 * 16 + ks1 * 8 + tg1;
    const int pA0 = tA0 ^ (((tA0 >> 5) & 1) << 2);
    const int pA4 = (tA0 + 4) ^ (((tA0 >> 5) & 1) << 2);
    const int pB0 = tA1 ^ (((tA1 >> 5) & 1) << 2);
    const int pB4 = (tA1 + 4) ^ (((tA1 >> 5) & 1) << 2);

    for (int w = 0; w < 7; ++w) {
        const float XA = ax1 + (w + 0.5f) * abw;
        const float xcA = fminf(fmaxf(XA, 0.f), 39.f);
        const int   x0A = (int)xcA, x1iA = min(x0A + 1, 39);
        const float lxA = xcA - (float)x0A;
        float a00 = (1.f - lyA) * (1.f - lxA), a01 = (1.f - lyA) * lxA;
        float a10 = lyA * (1.f - lxA),         a11 = lyA * lxA;
        if (!(vyA && XA > -1.f && XA < 40.f)) { a00 = a01 = a10 = a11 = 0.f; }
        const float XB = bx1 + (w + 0.5f) * bbw;
        const float xcB = fminf(fmaxf(XB, 0.f), 39.f);
        const int   x0B = (int)xcB, x1iB = min(x0B + 1, 39);
        const float lxB = xcB - (float)x0B;
        float b00 = (1.f - lyB) * (1.f - lxB), b01 = (1.f - lyB) * lxB;
        float b10 = lyB * (1.f - lxB),         b11 = lyB * lxB;
        if (!(vyB && XB > -1.f && XB < 40.f)) { b00 = b01 = b10 = b11 = 0.f; }

        U4 cA00, cA01, cA10, cA11, cB00, cB01, cB10, cB11;
        cA00.u = imgA[(y0A  * 40 + x0A ) * 32 + lane];
        cA01.u = imgA[(y0A  * 40 + x1iA) * 32 + lane];
        cA10.u = imgA[(y1iA * 40 + x0A ) * 32 + lane];
        cA11.u = imgA[(y1iA * 40 + x1iA) * 32 + lane];
        cB00.u = imgB[(y0B  * 40 + x0B ) * 32 + lane];
        cB01.u = imgB[(y0B  * 40 + x1iB) * 32 + lane];
        cB10.u = imgB[(y1iB * 40 + x0B ) * 32 + lane];
        cB11.u = imgB[(y1iB * 40 + x1iB) * 32 + lane];

        U4 oA, oB;
        #pragma unroll
        for (int j = 0; j < 4; ++j) {
            float2 f0 = __half22float2(cA00.h[j]);
            float2 f1 = __half22float2(cA01.h[j]);
            float2 f2 = __half22float2(cA10.h[j]);
            float2 f3 = __half22float2(cA11.h[j]);
            oA.h[j] = __floats2half2_rn(
                f0.x * a00 + f1.x * a01 + f2.x * a10 + f3.x * a11,
                f0.y * a00 + f1.y * a01 + f2.y * a10 + f3.y * a11);
            f0 = __half22float2(cB00.h[j]);
            f1 = __half22float2(cB01.h[j]);
            f2 = __half22float2(cB10.h[j]);
            f3 = __half22float2(cB11.h[j]);
            oB.h[j] = __floats2half2_rn(
                f0.x * b00 + f1.x * b01 + f2.x * b10 + f3.x * b11,
                f0.y * b00 + f1.y * b01 + f2.y * b10 + f3.y * b11);
        }
        *(uint4*)wrA = oA.u;
        *(uint4*)wrB = oB.u;
        __syncwarp();

        const int hw = h * 7 + w;
        {
            uint4 wv;
            wv.x = s[wp * 132 + pA0];
            wv.y = s[(wp + 8) * 132 + pA0];
            wv.z = s[wp * 132 + pA4];
            wv.w = s[(wp + 8) * 132 + pA4];
            *(uint4*)(outb + (size_t)(hw * 8 + cc0) * TILE_BYTES
                      + (ks0 * 32 + wp * 4 + tg0) * 16) = wv;
            wv.x = s[wp * 132 + pB0];
            wv.y = s[(wp + 8) * 132 + pB0];
            wv.z = s[wp * 132 + pB4];
            wv.w = s[(wp + 8) * 132 + pB4];
            *(uint4*)(outb + (size_t)(hw * 8 + cc1) * TILE_BYTES
                      + (ks1 * 32 + wp * 4 + tg1) * 16) = wv;
        }
        __syncwarp();
    }
}

// ===== fp16 MMA GEMM: 128x128x32 CTA, 8 warps (ks-split), 64x64 quad tiles =====
#define NSTAGE 4
#define STAGE_BYTES 16384
#define SM_TOTAL (NSTAGE * STAGE_BYTES)

__device__ __forceinline__ void cp16(void* smem_dst, const void* gmem_src) {
    unsigned s = (unsigned)__cvta_generic_to_shared(smem_dst);
    asm volatile("cp.async.cg.shared.global [%0], [%1], 16;" :: "r"(s), "l"(gmem_src));
}
__device__ __forceinline__ void cp_commit() { asm volatile("cp.async.commit_group;"); }
template<int N> __device__ __forceinline__ void cp_wait() {
    asm volatile("cp.async.wait_group %0;" :: "n"(N));
}

__global__ void __launch_bounds__(256, 1)
gemm_tc(const char* __restrict__ Afrag, const char* __restrict__ Bfrag, int nchunk,
        char* __restrict__ outFrag, float* __restrict__ outMax,
        const float* __restrict__ bias, const float* __restrict__ gamma,
        const float* __restrict__ beta, const float* __restrict__ mean,
        const float* __restrict__ var)
{
    extern __shared__ char sm[];
    const int tid = threadIdx.x, lane = tid & 31, wid = tid >> 5;
    const int ksw = wid >> 2;                 // k16-slice this warp owns
    const int wq  = wid & 3;                  // quad
    const int warp_m = wq >> 1, warp_n = wq & 1;
    const int ntile = blockIdx.x, mtile = blockIdx.y;

    const char* Ag = Afrag + (size_t)mtile * nchunk * TILE_BYTES;
    const char* Bg = Bfrag + (size_t)ntile * nchunk * TILE_BYTES;

    float acc[4][8][4];
    #pragma unroll
    for (int mt = 0; mt < 4; ++mt)
        #pragma unroll
        for (int nt = 0; nt < 8; ++nt)
            #pragma unroll
            for (int j = 0; j < 4; ++j) acc[mt][nt][j] = 0.f;

    #pragma unroll
    for (int t = 0; t < 3; ++t) {
        char* sa = sm + t * STAGE_BYTES;
        #pragma unroll
        for (int i = 0; i < 2; ++i) {
            const int off = (tid + i * 256) * 16;
            cp16(sa + off,        Ag + (size_t)t * TILE_BYTES + off);
            cp16(sa + 8192 + off, Bg + (size_t)t * TILE_BYTES + off);
        }
        cp_commit();
    }

    const int aBase = warp_m * 4096 + ksw * 512 + lane * 16;
    const int bBase = 8192 + warp_n * 4096 + ksw * 512 + lane * 16;

    for (int t = 0; t < nchunk; ++t) {
        cp_wait<2>();
        __syncthreads();

        if (t + 3 < nchunk) {
            char* sa = sm + ((t + 3) & 3) * STAGE_BYTES;
            #pragma unroll
            for (int i = 0; i < 2; ++i) {
                const int off = (tid + i * 256) * 16;
                cp16(sa + off,        Ag + (size_t)(t + 3) * TILE_BYTES + off);
                cp16(sa + 8192 + off, Bg + (size_t)(t + 3) * TILE_BYTES + off);
            }
        }
        cp_commit();

        const char* S = sm + (t & 3) * STAGE_BYTES;
        uint4 af[4];
        #pragma unroll
        for (int mt = 0; mt < 4; ++mt)
            af[mt] = *(const uint4*)(S + aBase + mt * 1024);
        uint4 bq[4];
        #pragma unroll
        for (int np = 0; np < 4; ++np)
            bq[np] = *(const uint4*)(S + bBase + np * 1024);
        #pragma unroll
        for (int np = 0; np < 4; ++np) {
            #pragma unroll
            for (int mt = 0; mt < 4; ++mt) {
                asm volatile(
                    "mma.sync.aligned.m16n8k16.row.col.f32.f16.f16.f32 "
                    "{%0,%1,%2,%3}, {%4,%5,%6,%7}, {%8,%9}, {%0,%1,%2,%3};"
                    : "+f"(acc[mt][np * 2][0]), "+f"(acc[mt][np * 2][1]),
                      "+f"(acc[mt][np * 2][2]), "+f"(acc[mt][np * 2][3])
                    : "r"(af[mt].x), "r"(af[mt].y), "r"(af[mt].z), "r"(af[mt].w),
                      "r"(bq[np].x), "r"(bq[np].y));
                asm volatile(
                    "mma.sync.aligned.m16n8k16.row.col.f32.f16.f16.f32 "
                    "{%0,%1,%2,%3}, {%4,%5,%6,%7}, {%8,%9}, {%0,%1,%2,%3};"
                    : "+f"(acc[mt][np * 2 + 1][0]), "+f"(acc[mt][np * 2 + 1][1]),
                      "+f"(acc[mt][np * 2 + 1][2]), "+f"(acc[mt][np * 2 + 1][3])
                    : "r"(af[mt].x), "r"(af[mt].y), "r"(af[mt].z), "r"(af[mt].w),
                      "r"(bq[np].z), "r"(bq[np].w));
            }
        }
    }

    const int g = lane >> 2, tg = lane & 3;

    // ---- ks-split combine: warps 4-7 dump partials, warps 0-3 add ----
    __syncthreads();
    {
        float2* red2 = (float2*)sm;   // 128 x 64 float2, XOR-swizzled by (g<<2)
        if (ksw == 1) {
            #pragma unroll
            for (int nt = 0; nt < 8; ++nt) {
                const int col2 = warp_n * 32 + nt * 4 + tg;
                #pragma unroll
                for (int mt = 0; mt < 4; ++mt) {
                    const int row = warp_m * 64 + mt * 16 + g;
                    const int ph = col2 ^ (g << 2);
                    float2 v0; v0.x = acc[mt][nt][0]; v0.y = acc[mt][nt][1];
                    float2 v1; v1.x = acc[mt][nt][2]; v1.y = acc[mt][nt][3];
                    red2[row * 64 + ph] = v0;
                    red2[(row + 8) * 64 + ph] = v1;
                }
            }
        }
        __syncthreads();
        if (ksw == 0) {
            #pragma unroll
            for (int nt = 0; nt < 8; ++nt) {
                const int col2 = warp_n * 32 + nt * 4 + tg;
                #pragma unroll
                for (int mt = 0; mt < 4; ++mt) {
                    const int row = warp_m * 64 + mt * 16 + g;
                    const int ph = col2 ^ (g << 2);
                    const float2 v0 = red2[row * 64 + ph];
                    const float2 v1 = red2[(row + 8) * 64 + ph];
                    acc[mt][nt][0] += v0.x; acc[mt][nt][1] += v0.y;
                    acc[mt][nt][2] += v1.x; acc[mt][nt][3] += v1.y;
                }
            }
        }
        __syncthreads();
    }

    if (outFrag) {
        // stage BN+ReLU tile in smem as half2 (stride 66), then emit A-frag fp16 tiles
        __half2* st2 = (__half2*)sm;
        if (ksw == 0) {
            #pragma unroll
            for (int nt = 0; nt < 8; ++nt) {
                const int c0l = warp_n * 64 + nt * 8 + tg * 2;
                const int cg0 = ntile * 128 + c0l;
                const float s0 = gamma[cg0]     * rsqrtf(var[cg0]     + EPS);
                const float s1 = gamma[cg0 + 1] * rsqrtf(var[cg0 + 1] + EPS);
                const float h0  = (bias[cg0]     - mean[cg0])     * s0 + beta[cg0];
                const float h1v = (bias[cg0 + 1] - mean[cg0 + 1]) * s1 + beta[cg0 + 1];
                #pragma unroll
                for (int mt = 0; mt < 4; ++mt) {
                    const int rowl = warp_m * 64 + mt * 16 + g;
                    st2[rowl * 66 + (c0l >> 1)] = __floats2half2_rn(
                        fmaxf(acc[mt][nt][0] * s0 + h0,  0.f),
                        fmaxf(acc[mt][nt][1] * s1 + h1v, 0.f));
                    st2[(rowl + 8) * 66 + (c0l >> 1)] = __floats2half2_rn(
                        fmaxf(acc[mt][nt][2] * s0 + h0,  0.f),
                        fmaxf(acc[mt][nt][3] * s1 + h1v, 0.f));
                }
            }
        }
        __syncthreads();
        char* dst = outFrag + (size_t)(mtile * 16 + ntile * 4) * TILE_BYTES;
        #pragma unroll
        for (int it = 0; it < 8; ++it) {
            const int u = tid + it * 256;        // 0..2047 (16B slots)
            const int chunkl = u >> 9, sidx = u & 511;
            const int subr = sidx >> 6, rem = sidx & 63;
            const int ks2 = rem >> 5, ln = rem & 31;
            const int g2 = ln >> 2, tg2 = ln & 3;
            const int row = subr * 16 + g2;
            const int kp = chunkl * 16 + ks2 * 8 + tg2;
            uint4 wv;
            wv.x = *(const uint32_t*)&st2[row * 66 + kp];
            wv.y = *(const uint32_t*)&st2[(row + 8) * 66 + kp];
            wv.z = *(const uint32_t*)&st2[row * 66 + kp + 4];
            wv.w = *(const uint32_t*)&st2[(row + 8) * 66 + kp + 4];
            *(uint4*)(dst + (size_t)chunkl * TILE_BYTES + subr * 1024 + rem * 16) = wv;
        }
    } else if (ksw == 0) {
        // fused BN + ReLU + max over 8-row groups -> outMax[node][col]
        const int n0 = ntile * 128 + warp_n * 64;
        #pragma unroll
        for (int nt = 0; nt < 8; ++nt) {
            const int c0 = n0 + nt * 8 + tg * 2;
            const float s0 = gamma[c0]     * rsqrtf(var[c0]     + EPS);
            const float s1 = gamma[c0 + 1] * rsqrtf(var[c0 + 1] + EPS);
            const float h0  = (bias[c0]     - mean[c0])     * s0 + beta[c0];
            const float h1v = (bias[c0 + 1] - mean[c0 + 1]) * s1 + beta[c0 + 1];
            #pragma unroll
            for (int mt = 0; mt < 4; ++mt) {
                float v0 = fmaxf(acc[mt][nt][0] * s0 + h0,  0.f);
                float v1 = fmaxf(acc[mt][nt][1] * s1 + h1v, 0.f);
                float v2 = fmaxf(acc[mt][nt][2] * s0 + h0,  0.f);
                float v3 = fmaxf(acc[mt][nt][3] * s1 + h1v, 0.f);
                #pragma unroll
                for (int d = 4; d <= 16; d <<= 1) {
                    v0 = fmaxf(v0, __shfl_xor_sync(0xffffffffu, v0, d));
                    v1 = fmaxf(v1, __shfl_xor_sync(0xffffffffu, v1, d));
                    v2 = fmaxf(v2, __shfl_xor_sync(0xffffffffu, v2, d));
                    v3 = fmaxf(v3, __shfl_xor_sync(0xffffffffu, v3, d));
                }
                if (lane < 4) {
                    const int node0 = mtile * 16 + warp_m * 8 + mt * 2;
                    float2 a; a.x = v0; a.y = v1;
                    float2 b; b.x = v2; b.y = v3;
                    *(float2*)&outMax[(size_t)node0 * DD + c0] = a;
                    *(float2*)&outMax[(size_t)(node0 + 1) * DD + c0] = b;
                }
            }
        }
    }
}

// ---------------- launch ----------------
extern "C" void kernel_launch(void* const* d_in, const int* in_sizes, int n_in,
                              void* d_out, int out_size)
{
    const float* images = (const float*)d_in[0];
    const int*   kf     = (const int*)  d_in[1];
    const float* boxes  = (const float*)d_in[2];
    const float* w1     = (const float*)d_in[3];
    const float* b1     = (const float*)d_in[4];
    const float* g1     = (const float*)d_in[5];
    const float* bt1    = (const float*)d_in[6];
    const float* m1     = (const float*)d_in[7];
    const float* v1     = (const float*)d_in[8];
    const float* w2     = (const float*)d_in[9];
    const float* b2     = (const float*)d_in[10];
    const float* g2     = (const float*)d_in[11];
    const float* bt2    = (const float*)d_in[12];
    const float* m2     = (const float*)d_in[13];
    const float* v2     = (const float*)d_in[14];
    float* out = (float*)d_out;

    char *roiT, *w1tT, *h1T, *w2T;
    cudaGetSymbolAddress((void**)&roiT, g_roiT);
    cudaGetSymbolAddress((void**)&w1tT, g_w1tT);
    cudaGetSymbolAddress((void**)&h1T,  g_h1T);
    cudaGetSymbolAddress((void**)&w2T,  g_w2T);

    cudaFuncSetAttribute(gemm_tc, cudaFuncAttributeMaxDynamicSharedMemorySize, SM_TOTAL);

    // order chosen so gemm1 is launch #4 (ncu capture slot)
    transpose_img<<<dim3(NPIX / 32, CCH / 64, NF), dim3(32, 8)>>>(images);
    transpose_w1<<<HID, 128>>>(w1);
    roi_gather_frag<<<dim3(256, 7), 256>>>(kf, boxes);
    gemm_tc<<<dim3(4, 32), 256, SM_TOTAL>>>(
        roiT, w1tT, NCHUNK, h1T, nullptr, b1, g1, bt1, m1, v1);
    repack_w2<<<DD, 128>>>(w2);
    gemm_tc<<<dim3(4, 32), 256, SM_TOTAL>>>(
        h1T, w2T, 16, nullptr, out, b2, g2, bt2, m2, v2);
}